// round 12
// baseline (speedup 1.0000x reference)
#include <cuda_runtime.h>
#include <cstdint>

// ============================================================
// ProtoMulHeadAttn  (WAY=5, SHOT=5, HEADS=12, DIM=768, L=512)
// Projections + attn1: mma.sync tf32, cvt done at staging.
// attn2: 3-phase parallel deterministic pipeline.
// ============================================================

#define WAYN   5
#define SHOTN  5
#define HEADSN 12
#define DIMN   768
#define LSEQ   512
#define HDN    64
#define NB     25            // WAY*SHOT
#define SCALE_F 0.125f       // 1/sqrt(64)
#define LCH    8             // attn2 L-chunks
#define LPC    (LSEQ / LCH)  // 64 tokens per chunk

// ---------------- scratch (static device memory; no allocs) ----------------
__device__ float g_q[NB * LSEQ * DIMN];
__device__ float g_k[NB * LSEQ * DIMN];
__device__ float g_v[NB * LSEQ * DIMN];
__device__ float g_a1[NB * DIMN];
__device__ float g_a2[NB * DIMN];
__device__ float g_attn[NB * DIMN];
__device__ float g_z[NB];
__device__ float g_c[WAYN * DIMN];
__device__ float g_s2p[WAYN * HEADSN * LCH * HDN * SHOTN * SHOTN];
__device__ float g_pw[WAYN * HEADSN * HDN * SHOTN * SHOTN];

__device__ __forceinline__ float negInf() { return __int_as_float(0xff800000); }

__device__ __forceinline__ void atomicMaxF(float* addr, float val) {
    int* ia = (int*)addr;
    int old = *ia;
    while (__int_as_float(old) < val) {
        int prev = atomicCAS(ia, old, __float_as_int(val));
        if (prev == old) break;
        old = prev;
    }
}

// ---------------- tf32 mma helpers ----------------
__device__ __forceinline__ uint32_t cvt_tf32(float f) {
    uint32_t u;
    asm("cvt.rna.tf32.f32 %0, %1;" : "=r"(u) : "f"(f));
    return u;
}
// round-to-tf32, result as float bit pattern (for smem staging)
__device__ __forceinline__ float tf32r(float f) {
    return __uint_as_float(cvt_tf32(f));
}
__device__ __forceinline__ float4 tf32r4(float4 v) {
    float4 r;
    r.x = tf32r(v.x); r.y = tf32r(v.y); r.z = tf32r(v.z); r.w = tf32r(v.w);
    return r;
}

__device__ __forceinline__ void mma_tf32(float* c, const uint32_t* a, const uint32_t* b) {
    asm volatile(
        "mma.sync.aligned.m16n8k8.row.col.f32.tf32.tf32.f32 "
        "{%0,%1,%2,%3}, {%4,%5,%6,%7}, {%8,%9}, {%0,%1,%2,%3};"
        : "+f"(c[0]), "+f"(c[1]), "+f"(c[2]), "+f"(c[3])
        : "r"(a[0]), "r"(a[1]), "r"(a[2]), "r"(a[3]),
          "r"(b[0]), "r"(b[1]));
}

// ============================================================
// 1) Projection GEMM via tf32 mma.sync; smem holds pre-rounded
//    tf32 values (cvt at staging, fragments are plain LDS).
// ============================================================
#define KC   16
#define PADK 20
#define NKIT (DIMN / KC)     // 48

__global__ __launch_bounds__(256) void gemm_tc_kernel(
    const float* __restrict__ A,
    const float* __restrict__ W0, const float* __restrict__ W1, const float* __restrict__ W2,
    const float* __restrict__ b0, const float* __restrict__ b1, const float* __restrict__ b2,
    float* __restrict__ o0, float* __restrict__ o1, float* __restrict__ o2)
{
    __shared__ __align__(16) float As[2][128 * PADK];
    __shared__ __align__(16) float Bs[2][128 * PADK];

    const int tid = threadIdx.x;
    const int wid = tid >> 5, lane = tid & 31;
    const int g = lane >> 2, tig = lane & 3;
    const int wm = (wid >> 2) * 64;
    const int wn = (wid & 3) * 32;
    const int n0 = blockIdx.x * 128;
    const int m0 = blockIdx.y * 128;
    const int which = blockIdx.z;
    const float* W    = (which == 0) ? W0 : (which == 1) ? W1 : W2;
    const float* bias = (which == 0) ? b0 : (which == 1) ? b1 : b2;
    float* Cout       = (which == 0) ? o0 : (which == 1) ? o1 : o2;

    const float* Ag = A + (size_t)m0 * DIMN;
    const float* Wg = W + (size_t)n0 * DIMN;

    float c[4][4][4];
#pragma unroll
    for (int mf = 0; mf < 4; mf++)
#pragma unroll
        for (int nf = 0; nf < 4; nf++)
#pragma unroll
            for (int r = 0; r < 4; r++) c[mf][nf][r] = 0.f;

#pragma unroll
    for (int u = 0; u < 2; u++) {
        int idx = tid + u * 256;
        int r = idx >> 2, c4 = (idx & 3) << 2;
        *(float4*)&As[0][r * PADK + c4] = tf32r4(*(const float4*)&Ag[(size_t)r * DIMN + c4]);
        *(float4*)&Bs[0][r * PADK + c4] = tf32r4(*(const float4*)&Wg[(size_t)r * DIMN + c4]);
    }
    __syncthreads();

    float4 pa[2], pb[2];
    for (int it = 0; it < NKIT; it++) {
        const int s = it & 1;
        if (it + 1 < NKIT) {
            const int kn = (it + 1) * KC;
#pragma unroll
            for (int u = 0; u < 2; u++) {
                int idx = tid + u * 256;
                int r = idx >> 2, c4 = (idx & 3) << 2;
                pa[u] = *(const float4*)&Ag[(size_t)r * DIMN + kn + c4];
                pb[u] = *(const float4*)&Wg[(size_t)r * DIMN + kn + c4];
            }
        }

#pragma unroll
        for (int ks = 0; ks < 2; ks++) {
            uint32_t af[4][4], bf[4][2];
#pragma unroll
            for (int mf = 0; mf < 4; mf++) {
                int rb = (wm + mf * 16 + g) * PADK + ks * 8 + tig;
                af[mf][0] = __float_as_uint(As[s][rb]);
                af[mf][1] = __float_as_uint(As[s][rb + 8 * PADK]);
                af[mf][2] = __float_as_uint(As[s][rb + 4]);
                af[mf][3] = __float_as_uint(As[s][rb + 8 * PADK + 4]);
            }
#pragma unroll
            for (int nf = 0; nf < 4; nf++) {
                int rb = (wn + nf * 8 + g) * PADK + ks * 8 + tig;
                bf[nf][0] = __float_as_uint(Bs[s][rb]);
                bf[nf][1] = __float_as_uint(Bs[s][rb + 4]);
            }
#pragma unroll
            for (int mf = 0; mf < 4; mf++)
#pragma unroll
                for (int nf = 0; nf < 4; nf++)
                    mma_tf32(c[mf][nf], af[mf], bf[nf]);
        }

        if (it + 1 < NKIT) {
            const int sn = s ^ 1;
#pragma unroll
            for (int u = 0; u < 2; u++) {
                int idx = tid + u * 256;
                int r = idx >> 2, c4 = (idx & 3) << 2;
                *(float4*)&As[sn][r * PADK + c4] = tf32r4(pa[u]);
                *(float4*)&Bs[sn][r * PADK + c4] = tf32r4(pb[u]);
            }
        }
        __syncthreads();
    }

#pragma unroll
    for (int mf = 0; mf < 4; mf++) {
        int row = m0 + wm + mf * 16 + g;
#pragma unroll
        for (int nf = 0; nf < 4; nf++) {
            int col = n0 + wn + nf * 8 + tig * 2;
            float bx = bias[col], by = bias[col + 1];
            float2 v0 = {c[mf][nf][0] + bx, c[mf][nf][1] + by};
            float2 v1 = {c[mf][nf][2] + bx, c[mf][nf][3] + by};
            *(float2*)&Cout[(size_t)row * DIMN + col] = v0;
            *(float2*)&Cout[(size_t)(row + 8) * DIMN + col] = v1;
        }
    }
}

// ============================================================
// 2) init a1/a2 to -inf (atomicMax targets)
// ============================================================
__global__ void init_kernel() {
    int i = blockIdx.x * 256 + threadIdx.x;
    if (i < NB * DIMN) g_a1[i] = negInf();
    else if (i < 2 * NB * DIMN) g_a2[i - NB * DIMN] = negInf();
}

// ============================================================
// 3) Branch-1 flash attention via tf32 mma + fused max-pool.
//    K/V/P pre-rounded to tf32 at their smem writes.
// ============================================================
#define AKT  32
#define PSS  36
#define KSS  68
#define VSS  72

__global__ __launch_bounds__(256) void attn1_kernel() {
    __shared__ __align__(16) float Ps[128 * PSS];
    __shared__ __align__(16) float Ks[AKT * KSS];
    __shared__ __align__(16) float Vs[AKT * VSS];

    const int tid = threadIdx.x;
    const int wid = tid >> 5, lane = tid & 31;
    const int g = lane >> 2, tig = lane & 3;
    const int qt = blockIdx.x, h = blockIdx.y, b = blockIdx.z;

    const float* qbase = g_q + ((size_t)b * LSEQ + qt * 128) * DIMN + h * HDN;
    const float* kbase = g_k + (size_t)b * LSEQ * DIMN + h * HDN;
    const float* vbase = g_v + (size_t)b * LSEQ * DIMN + h * HDN;

    float* prow0 = &Ps[(wid * 16 + g) * PSS];
    float* prow1 = &Ps[(wid * 16 + g + 8) * PSS];

    // ---- Q fragments (persistent), staged in two 32-col halves ----
    uint32_t aq[8][4];
#pragma unroll
    for (int half = 0; half < 2; half++) {
        __syncthreads();
        for (int i = tid; i < 128 * 32; i += 256) {
            int r = i >> 5, d = i & 31;
            Ps[r * PSS + d] = qbase[(size_t)r * DIMN + half * 32 + d] * SCALE_F;
        }
        __syncthreads();
#pragma unroll
        for (int k2 = 0; k2 < 4; k2++) {
            int kk = half * 4 + k2;
            aq[kk][0] = cvt_tf32(prow0[k2 * 8 + tig]);
            aq[kk][1] = cvt_tf32(prow1[k2 * 8 + tig]);
            aq[kk][2] = cvt_tf32(prow0[k2 * 8 + tig + 4]);
            aq[kk][3] = cvt_tf32(prow1[k2 * 8 + tig + 4]);
        }
    }

    float o[8][4];
#pragma unroll
    for (int nf = 0; nf < 8; nf++)
#pragma unroll
        for (int r = 0; r < 4; r++) o[nf][r] = 0.f;
    float m0 = negInf(), m1 = negInf(), l0s = 0.f, l1s = 0.f;

    for (int kt = 0; kt < LSEQ / AKT; kt++) {
        __syncthreads();
        for (int i = tid; i < AKT * 16; i += 256) {
            int r = i >> 4, c4 = (i & 15) * 4;
            *(float4*)&Ks[r * KSS + c4] =
                tf32r4(*(const float4*)&kbase[((size_t)kt * AKT + r) * DIMN + c4]);
            *(float4*)&Vs[r * VSS + c4] =
                tf32r4(*(const float4*)&vbase[((size_t)kt * AKT + r) * DIMN + c4]);
        }
        __syncthreads();

        // ---- scores S = Q K^T ----
        float s[4][4];
#pragma unroll
        for (int nf = 0; nf < 4; nf++)
#pragma unroll
            for (int r = 0; r < 4; r++) s[nf][r] = 0.f;
#pragma unroll
        for (int kk = 0; kk < 8; kk++) {
#pragma unroll
            for (int nf = 0; nf < 4; nf++) {
                uint32_t bb[2];
                bb[0] = __float_as_uint(Ks[(nf * 8 + g) * KSS + kk * 8 + tig]);
                bb[1] = __float_as_uint(Ks[(nf * 8 + g) * KSS + kk * 8 + tig + 4]);
                mma_tf32(s[nf], aq[kk], bb);
            }
        }

        // ---- online softmax (rows g, g+8) ----
        float t0 = negInf(), t1 = negInf();
#pragma unroll
        for (int nf = 0; nf < 4; nf++) {
            t0 = fmaxf(t0, fmaxf(s[nf][0], s[nf][1]));
            t1 = fmaxf(t1, fmaxf(s[nf][2], s[nf][3]));
        }
#pragma unroll
        for (int off = 1; off < 4; off <<= 1) {
            t0 = fmaxf(t0, __shfl_xor_sync(0xffffffffu, t0, off));
            t1 = fmaxf(t1, __shfl_xor_sync(0xffffffffu, t1, off));
        }
        float mn0 = fmaxf(m0, t0), mn1 = fmaxf(m1, t1);
        float c0 = __expf(m0 - mn0), c1 = __expf(m1 - mn1);
        l0s *= c0; l1s *= c1;
#pragma unroll
        for (int nf = 0; nf < 8; nf++) {
            o[nf][0] *= c0; o[nf][1] *= c0;
            o[nf][2] *= c1; o[nf][3] *= c1;
        }
        float ls0 = 0.f, ls1 = 0.f;
#pragma unroll
        for (int nf = 0; nf < 4; nf++) {
            float p0 = __expf(s[nf][0] - mn0);
            float p1 = __expf(s[nf][1] - mn0);
            float p2 = __expf(s[nf][2] - mn1);
            float p3 = __expf(s[nf][3] - mn1);
            ls0 += p0 + p1; ls1 += p2 + p3;
            prow0[nf * 8 + 2 * tig]     = tf32r(p0);
            prow0[nf * 8 + 2 * tig + 1] = tf32r(p1);
            prow1[nf * 8 + 2 * tig]     = tf32r(p2);
            prow1[nf * 8 + 2 * tig + 1] = tf32r(p3);
        }
#pragma unroll
        for (int off = 1; off < 4; off <<= 1) {
            ls0 += __shfl_xor_sync(0xffffffffu, ls0, off);
            ls1 += __shfl_xor_sync(0xffffffffu, ls1, off);
        }
        l0s += ls0; l1s += ls1;
        m0 = mn0; m1 = mn1;
        __syncwarp();

        // ---- O += P V ----
#pragma unroll
        for (int kk = 0; kk < 4; kk++) {
            uint32_t ap[4];
            ap[0] = __float_as_uint(prow0[kk * 8 + tig]);
            ap[1] = __float_as_uint(prow1[kk * 8 + tig]);
            ap[2] = __float_as_uint(prow0[kk * 8 + tig + 4]);
            ap[3] = __float_as_uint(prow1[kk * 8 + tig + 4]);
#pragma unroll
            for (int nf = 0; nf < 8; nf++) {
                uint32_t bb[2];
                bb[0] = __float_as_uint(Vs[(kk * 8 + tig) * VSS + nf * 8 + g]);
                bb[1] = __float_as_uint(Vs[(kk * 8 + tig + 4) * VSS + nf * 8 + g]);
                mma_tf32(o[nf], ap, bb);
            }
        }
    }

    // ---- normalize + max-pool via staging, two 32-dim halves ----
    float inv0 = 1.f / l0s, inv1 = 1.f / l1s;
#pragma unroll
    for (int nf = 0; nf < 8; nf++) {
        o[nf][0] *= inv0; o[nf][1] *= inv0;
        o[nf][2] *= inv1; o[nf][3] *= inv1;
    }
#pragma unroll
    for (int half = 0; half < 2; half++) {
        __syncthreads();
#pragma unroll
        for (int nf2 = 0; nf2 < 4; nf2++) {
            int nf = half * 4 + nf2;
            prow0[nf2 * 8 + 2 * tig]     = o[nf][0];
            prow0[nf2 * 8 + 2 * tig + 1] = o[nf][1];
            prow1[nf2 * 8 + 2 * tig]     = o[nf][2];
            prow1[nf2 * 8 + 2 * tig + 1] = o[nf][3];
        }
        __syncthreads();
        if (tid < 32) {
            float mx = negInf();
            for (int r = 0; r < 128; r++) mx = fmaxf(mx, Ps[r * PSS + tid]);
            atomicMaxF(&g_a1[b * DIMN + h * HDN + half * 32 + tid], mx);
        }
    }
}

// ============================================================
// 4a) attn2 phase A: partial channel scores over one L-chunk.
// ============================================================
__global__ __launch_bounds__(320) void attn2_score_kernel() {
    __shared__ float s_a[8 * 5 * 64];
    __shared__ float s_b[8 * 5 * 64];

    const int d = threadIdx.x, s = threadIdx.y;
    const int tid = s * 64 + d;
    const int wh = blockIdx.x, lc = blockIdx.y;
    const int w = wh / HEADSN, h = wh % HEADSN;

    const float* qb = g_q + (size_t)w * SHOTN * LSEQ * DIMN + h * HDN;
    const float* kb = g_k + (size_t)w * SHOTN * LSEQ * DIMN + h * HDN;

    float acc[5] = {0.f, 0.f, 0.f, 0.f, 0.f};

    for (int l0 = 0; l0 < LPC; l0 += 8) {
        __syncthreads();
        for (int i = tid; i < 2560; i += 320) {
            int dd = i & 63, tt = (i >> 6) % 5, li = i / 320;
            size_t off = ((size_t)tt * LSEQ + lc * LPC + l0 + li) * DIMN + dd;
            s_a[i] = qb[off];
            s_b[i] = kb[off];
        }
        __syncthreads();
#pragma unroll
        for (int li = 0; li < 8; li++) {
            float qv = s_a[li * 320 + s * 64 + d];
#pragma unroll
            for (int t = 0; t < 5; t++)
                acc[t] += qv * s_b[li * 320 + t * 64 + d];
        }
    }

    float* dst = g_s2p + (((size_t)wh * LCH + lc) * HDN + d) * 25 + s * 5;
#pragma unroll
    for (int t = 0; t < 5; t++) dst[t] = acc[t];
}

// ============================================================
// 4b) attn2 phase B: ordered reduce + softmax -> pw
// ============================================================
__global__ __launch_bounds__(320) void attn2_softmax_kernel() {
    const int d = threadIdx.x, s = threadIdx.y;
    const int wh = blockIdx.x;

    float acc[5];
#pragma unroll
    for (int t = 0; t < 5; t++) {
        float v = 0.f;
#pragma unroll
        for (int c = 0; c < LCH; c++)
            v += g_s2p[(((size_t)wh * LCH + c) * HDN + d) * 25 + s * 5 + t];
        acc[t] = v * SCALE_F;
    }

    float mx = negInf();
#pragma unroll
    for (int t = 0; t < 5; t++) mx = fmaxf(mx, acc[t]);
    float pw[5], sum = 0.f;
#pragma unroll
    for (int t = 0; t < 5; t++) { pw[t] = __expf(acc[t] - mx); sum += pw[t]; }
    float inv = 1.f / sum;
#pragma unroll
    for (int t = 0; t < 5; t++)
        g_pw[((size_t)wh * HDN + d) * 25 + s * 5 + t] = pw[t] * inv;
}

// ============================================================
// 4c) attn2 phase C: weighted V + max-pool, atomicMax.
// ============================================================
__global__ __launch_bounds__(320) void attn2_apply_kernel() {
    __shared__ float s_v[8 * 5 * 64];

    const int d = threadIdx.x, s = threadIdx.y;
    const int tid = s * 64 + d;
    const int wh = blockIdx.x, lc = blockIdx.y;
    const int w = wh / HEADSN, h = wh % HEADSN;

    const float* vb = g_v + (size_t)w * SHOTN * LSEQ * DIMN + h * HDN;

    float pw[5];
#pragma unroll
    for (int t = 0; t < 5; t++)
        pw[t] = g_pw[((size_t)wh * HDN + d) * 25 + s * 5 + t];

    float amax = negInf();
    for (int l0 = 0; l0 < LPC; l0 += 8) {
        __syncthreads();
        for (int i = tid; i < 2560; i += 320) {
            int dd = i & 63, tt = (i >> 6) % 5, li = i / 320;
            s_v[i] = vb[((size_t)tt * LSEQ + lc * LPC + l0 + li) * DIMN + dd];
        }
        __syncthreads();
#pragma unroll
        for (int li = 0; li < 8; li++) {
            float val = 0.f;
#pragma unroll
            for (int t = 0; t < 5; t++)
                val += pw[t] * s_v[li * 320 + t * 64 + d];
            amax = fmaxf(amax, val);
        }
    }

    atomicMaxF(&g_a2[((size_t)w * SHOTN + s) * DIMN + h * HDN + d], amax);
}

// ============================================================
// 5) LayerNorm both branches + combine + tanh-dot with wp
// ============================================================
__device__ __forceinline__ float blockReduceSum256(float v, float* red) {
#pragma unroll
    for (int o = 16; o > 0; o >>= 1) v += __shfl_down_sync(0xffffffffu, v, o);
    __syncthreads();
    if ((threadIdx.x & 31) == 0) red[threadIdx.x >> 5] = v;
    __syncthreads();
    float tot = 0.f;
#pragma unroll
    for (int i = 0; i < 8; i++) tot += red[i];
    return tot;
}

__global__ __launch_bounds__(256) void ln_kernel(
    const float* __restrict__ gamma, const float* __restrict__ beta,
    const float* __restrict__ wp, const float* __restrict__ bp)
{
    __shared__ float red[8];
    const int row = blockIdx.x, tid = threadIdx.x;
    const float* r1 = g_a1 + row * DIMN;
    const float* r2 = g_a2 + row * DIMN;

    float s1 = 0, q1 = 0, s2 = 0, q2 = 0;
    for (int j = tid; j < DIMN; j += 256) {
        float x = r1[j]; s1 += x; q1 += x * x;
        float y = r2[j]; s2 += y; q2 += y * y;
    }
    s1 = blockReduceSum256(s1, red);
    q1 = blockReduceSum256(q1, red);
    s2 = blockReduceSum256(s2, red);
    q2 = blockReduceSum256(q2, red);

    const float invd = 1.f / DIMN;
    float m1 = s1 * invd, m2 = s2 * invd;
    float rs1 = rsqrtf(q1 * invd - m1 * m1 + 1e-5f);
    float rs2 = rsqrtf(q2 * invd - m2 * m2 + 1e-5f);

    float dotv = 0.f;
    for (int j = tid; j < DIMN; j += 256) {
        float g = gamma[j], bb = beta[j];
        float l1 = (r1[j] - m1) * rs1 * g + bb;
        float l2 = (r2[j] - m2) * rs2 * g + bb;
        float at = 0.5f * (l1 + l2);
        g_attn[row * DIMN + j] = at;
        dotv += tanhf(at) * wp[j];
    }
    dotv = blockReduceSum256(dotv, red);
    if (tid == 0) g_z[row] = dotv + bp[0];
}

// ============================================================
// 6) softmax over shots + weighted sum of attn -> c[w, dim]
// ============================================================
__global__ __launch_bounds__(256) void weight_kernel() {
    const int w = blockIdx.x, tid = threadIdx.x;
    float zz[5], mx = negInf();
#pragma unroll
    for (int t = 0; t < 5; t++) { zz[t] = g_z[w * 5 + t]; mx = fmaxf(mx, zz[t]); }
    float pw[5], sum = 0.f;
#pragma unroll
    for (int t = 0; t < 5; t++) { pw[t] = __expf(zz[t] - mx); sum += pw[t]; }
    float inv = 1.f / sum;
    for (int j = tid; j < DIMN; j += 256) {
        float acc = 0.f;
#pragma unroll
        for (int t = 0; t < 5; t++)
            acc += pw[t] * g_attn[((size_t)w * 5 + t) * DIMN + j];
        g_c[w * DIMN + j] = acc * inv;
    }
}

// ============================================================
// 7) out[w,j] = c[w,:] . Wo[j,:] + SHOT*bo[j]
// ============================================================
__global__ __launch_bounds__(256) void out_kernel(
    const float* __restrict__ Wo, const float* __restrict__ bo,
    float* __restrict__ out)
{
    const int w = blockIdx.y;
    const int warp = threadIdx.x >> 5, lane = threadIdx.x & 31;
    const int j = blockIdx.x * 8 + warp;
    const float* cr = g_c + w * DIMN;
    const float* wr = Wo + (size_t)j * DIMN;
    float s = 0.f;
    for (int kk = lane; kk < DIMN; kk += 32) s += cr[kk] * wr[kk];
#pragma unroll
    for (int o = 16; o > 0; o >>= 1) s += __shfl_down_sync(0xffffffffu, s, o);
    if (lane == 0) out[w * DIMN + j] = s + (float)SHOTN * bo[j];
}

// ============================================================
// launcher
// ============================================================
extern "C" void kernel_launch(void* const* d_in, const int* in_sizes, int n_in,
                              void* d_out, int out_size)
{
    const float* x     = (const float*)d_in[0];
    const float* Wq    = (const float*)d_in[1];
    const float* bq    = (const float*)d_in[2];
    const float* Wk    = (const float*)d_in[3];
    const float* bk    = (const float*)d_in[4];
    const float* Wv    = (const float*)d_in[5];
    const float* bv    = (const float*)d_in[6];
    const float* gamma = (const float*)d_in[7];
    const float* beta  = (const float*)d_in[8];
    const float* wp    = (const float*)d_in[9];
    const float* bp    = (const float*)d_in[10];
    const float* Wo    = (const float*)d_in[11];
    const float* bo    = (const float*)d_in[12];
    float* out = (float*)d_out;

    float *qp, *kp, *vp;
    cudaGetSymbolAddress((void**)&qp, g_q);
    cudaGetSymbolAddress((void**)&kp, g_k);
    cudaGetSymbolAddress((void**)&vp, g_v);

    gemm_tc_kernel<<<dim3(DIMN / 128, (NB * LSEQ) / 128, 3), 256>>>(
        x, Wq, Wk, Wv, bq, bk, bv, qp, kp, vp);

    init_kernel<<<(2 * NB * DIMN + 255) / 256, 256>>>();

    dim3 agrid(LSEQ / 128, HEADSN, NB);          // (4, 12, 25)
    attn1_kernel<<<agrid, 256>>>();

    attn2_score_kernel<<<dim3(WAYN * HEADSN, LCH), dim3(64, 5)>>>();
    attn2_softmax_kernel<<<WAYN * HEADSN, dim3(64, 5)>>>();
    attn2_apply_kernel<<<dim3(WAYN * HEADSN, LCH), dim3(64, 5)>>>();

    ln_kernel<<<NB, 256>>>(gamma, beta, wp, bp);
    weight_kernel<<<WAYN, 256>>>();
    out_kernel<<<dim3(DIMN / 8, WAYN), 256>>>(Wo, bo, out);
}

// round 13
// speedup vs baseline: 1.0006x; 1.0006x over previous
#include <cuda_runtime.h>
#include <cstdint>

// ============================================================
// ProtoMulHeadAttn  (WAY=5, SHOT=5, HEADS=12, DIM=768, L=512)
// Projections + attn1: mma.sync tf32, cvt done at staging.
// attn2: 3-phase parallel deterministic pipeline.
// ============================================================

#define WAYN   5
#define SHOTN  5
#define HEADSN 12
#define DIMN   768
#define LSEQ   512
#define HDN    64
#define NB     25            // WAY*SHOT
#define SCALE_F 0.125f       // 1/sqrt(64)
#define LCH    8             // attn2 L-chunks
#define LPC    (LSEQ / LCH)  // 64 tokens per chunk

// ---------------- scratch (static device memory; no allocs) ----------------
__device__ float g_q[NB * LSEQ * DIMN];
__device__ float g_k[NB * LSEQ * DIMN];
__device__ float g_v[NB * LSEQ * DIMN];
__device__ float g_a1[NB * DIMN];
__device__ float g_a2[NB * DIMN];
__device__ float g_attn[NB * DIMN];
__device__ float g_z[NB];
__device__ float g_c[WAYN * DIMN];
__device__ float g_s2p[WAYN * HEADSN * LCH * HDN * SHOTN * SHOTN];
__device__ float g_pw[WAYN * HEADSN * HDN * SHOTN * SHOTN];

__device__ __forceinline__ float negInf() { return __int_as_float(0xff800000); }

__device__ __forceinline__ void atomicMaxF(float* addr, float val) {
    int* ia = (int*)addr;
    int old = *ia;
    while (__int_as_float(old) < val) {
        int prev = atomicCAS(ia, old, __float_as_int(val));
        if (prev == old) break;
        old = prev;
    }
}

// ---------------- tf32 mma helpers ----------------
__device__ __forceinline__ uint32_t cvt_tf32(float f) {
    uint32_t u;
    asm("cvt.rna.tf32.f32 %0, %1;" : "=r"(u) : "f"(f));
    return u;
}
// round-to-tf32, result as float bit pattern (for smem staging)
__device__ __forceinline__ float tf32r(float f) {
    return __uint_as_float(cvt_tf32(f));
}
__device__ __forceinline__ float4 tf32r4(float4 v) {
    float4 r;
    r.x = tf32r(v.x); r.y = tf32r(v.y); r.z = tf32r(v.z); r.w = tf32r(v.w);
    return r;
}

__device__ __forceinline__ void mma_tf32(float* c, const uint32_t* a, const uint32_t* b) {
    asm volatile(
        "mma.sync.aligned.m16n8k8.row.col.f32.tf32.tf32.f32 "
        "{%0,%1,%2,%3}, {%4,%5,%6,%7}, {%8,%9}, {%0,%1,%2,%3};"
        : "+f"(c[0]), "+f"(c[1]), "+f"(c[2]), "+f"(c[3])
        : "r"(a[0]), "r"(a[1]), "r"(a[2]), "r"(a[3]),
          "r"(b[0]), "r"(b[1]));
}

// ============================================================
// 1) Projection GEMM via tf32 mma.sync; smem holds pre-rounded
//    tf32 values (cvt at staging, fragments are plain LDS).
// ============================================================
#define KC   16
#define PADK 20
#define NKIT (DIMN / KC)     // 48

__global__ __launch_bounds__(256) void gemm_tc_kernel(
    const float* __restrict__ A,
    const float* __restrict__ W0, const float* __restrict__ W1, const float* __restrict__ W2,
    const float* __restrict__ b0, const float* __restrict__ b1, const float* __restrict__ b2,
    float* __restrict__ o0, float* __restrict__ o1, float* __restrict__ o2)
{
    __shared__ __align__(16) float As[2][128 * PADK];
    __shared__ __align__(16) float Bs[2][128 * PADK];

    const int tid = threadIdx.x;
    const int wid = tid >> 5, lane = tid & 31;
    const int g = lane >> 2, tig = lane & 3;
    const int wm = (wid >> 2) * 64;
    const int wn = (wid & 3) * 32;
    const int n0 = blockIdx.x * 128;
    const int m0 = blockIdx.y * 128;
    const int which = blockIdx.z;
    const float* W    = (which == 0) ? W0 : (which == 1) ? W1 : W2;
    const float* bias = (which == 0) ? b0 : (which == 1) ? b1 : b2;
    float* Cout       = (which == 0) ? o0 : (which == 1) ? o1 : o2;

    const float* Ag = A + (size_t)m0 * DIMN;
    const float* Wg = W + (size_t)n0 * DIMN;

    float c[4][4][4];
#pragma unroll
    for (int mf = 0; mf < 4; mf++)
#pragma unroll
        for (int nf = 0; nf < 4; nf++)
#pragma unroll
            for (int r = 0; r < 4; r++) c[mf][nf][r] = 0.f;

#pragma unroll
    for (int u = 0; u < 2; u++) {
        int idx = tid + u * 256;
        int r = idx >> 2, c4 = (idx & 3) << 2;
        *(float4*)&As[0][r * PADK + c4] = tf32r4(*(const float4*)&Ag[(size_t)r * DIMN + c4]);
        *(float4*)&Bs[0][r * PADK + c4] = tf32r4(*(const float4*)&Wg[(size_t)r * DIMN + c4]);
    }
    __syncthreads();

    float4 pa[2], pb[2];
    for (int it = 0; it < NKIT; it++) {
        const int s = it & 1;
        if (it + 1 < NKIT) {
            const int kn = (it + 1) * KC;
#pragma unroll
            for (int u = 0; u < 2; u++) {
                int idx = tid + u * 256;
                int r = idx >> 2, c4 = (idx & 3) << 2;
                pa[u] = *(const float4*)&Ag[(size_t)r * DIMN + kn + c4];
                pb[u] = *(const float4*)&Wg[(size_t)r * DIMN + kn + c4];
            }
        }

#pragma unroll
        for (int ks = 0; ks < 2; ks++) {
            uint32_t af[4][4], bf[4][2];
#pragma unroll
            for (int mf = 0; mf < 4; mf++) {
                int rb = (wm + mf * 16 + g) * PADK + ks * 8 + tig;
                af[mf][0] = __float_as_uint(As[s][rb]);
                af[mf][1] = __float_as_uint(As[s][rb + 8 * PADK]);
                af[mf][2] = __float_as_uint(As[s][rb + 4]);
                af[mf][3] = __float_as_uint(As[s][rb + 8 * PADK + 4]);
            }
#pragma unroll
            for (int nf = 0; nf < 4; nf++) {
                int rb = (wn + nf * 8 + g) * PADK + ks * 8 + tig;
                bf[nf][0] = __float_as_uint(Bs[s][rb]);
                bf[nf][1] = __float_as_uint(Bs[s][rb + 4]);
            }
#pragma unroll
            for (int mf = 0; mf < 4; mf++)
#pragma unroll
                for (int nf = 0; nf < 4; nf++)
                    mma_tf32(c[mf][nf], af[mf], bf[nf]);
        }

        if (it + 1 < NKIT) {
            const int sn = s ^ 1;
#pragma unroll
            for (int u = 0; u < 2; u++) {
                int idx = tid + u * 256;
                int r = idx >> 2, c4 = (idx & 3) << 2;
                *(float4*)&As[sn][r * PADK + c4] = tf32r4(pa[u]);
                *(float4*)&Bs[sn][r * PADK + c4] = tf32r4(pb[u]);
            }
        }
        __syncthreads();
    }

#pragma unroll
    for (int mf = 0; mf < 4; mf++) {
        int row = m0 + wm + mf * 16 + g;
#pragma unroll
        for (int nf = 0; nf < 4; nf++) {
            int col = n0 + wn + nf * 8 + tig * 2;
            float bx = bias[col], by = bias[col + 1];
            float2 v0 = {c[mf][nf][0] + bx, c[mf][nf][1] + by};
            float2 v1 = {c[mf][nf][2] + bx, c[mf][nf][3] + by};
            *(float2*)&Cout[(size_t)row * DIMN + col] = v0;
            *(float2*)&Cout[(size_t)(row + 8) * DIMN + col] = v1;
        }
    }
}

// ============================================================
// 2) init a1/a2 to -inf (atomicMax targets)
// ============================================================
__global__ void init_kernel() {
    int i = blockIdx.x * 256 + threadIdx.x;
    if (i < NB * DIMN) g_a1[i] = negInf();
    else if (i < 2 * NB * DIMN) g_a2[i - NB * DIMN] = negInf();
}

// ============================================================
// 3) Branch-1 flash attention via tf32 mma + fused max-pool.
//    K/V/P pre-rounded to tf32 at their smem writes.
// ============================================================
#define AKT  32
#define PSS  36
#define KSS  68
#define VSS  72

__global__ __launch_bounds__(256) void attn1_kernel() {
    __shared__ __align__(16) float Ps[128 * PSS];
    __shared__ __align__(16) float Ks[AKT * KSS];
    __shared__ __align__(16) float Vs[AKT * VSS];

    const int tid = threadIdx.x;
    const int wid = tid >> 5, lane = tid & 31;
    const int g = lane >> 2, tig = lane & 3;
    const int qt = blockIdx.x, h = blockIdx.y, b = blockIdx.z;

    const float* qbase = g_q + ((size_t)b * LSEQ + qt * 128) * DIMN + h * HDN;
    const float* kbase = g_k + (size_t)b * LSEQ * DIMN + h * HDN;
    const float* vbase = g_v + (size_t)b * LSEQ * DIMN + h * HDN;

    float* prow0 = &Ps[(wid * 16 + g) * PSS];
    float* prow1 = &Ps[(wid * 16 + g + 8) * PSS];

    // ---- Q fragments (persistent), staged in two 32-col halves ----
    uint32_t aq[8][4];
#pragma unroll
    for (int half = 0; half < 2; half++) {
        __syncthreads();
        for (int i = tid; i < 128 * 32; i += 256) {
            int r = i >> 5, d = i & 31;
            Ps[r * PSS + d] = qbase[(size_t)r * DIMN + half * 32 + d] * SCALE_F;
        }
        __syncthreads();
#pragma unroll
        for (int k2 = 0; k2 < 4; k2++) {
            int kk = half * 4 + k2;
            aq[kk][0] = cvt_tf32(prow0[k2 * 8 + tig]);
            aq[kk][1] = cvt_tf32(prow1[k2 * 8 + tig]);
            aq[kk][2] = cvt_tf32(prow0[k2 * 8 + tig + 4]);
            aq[kk][3] = cvt_tf32(prow1[k2 * 8 + tig + 4]);
        }
    }

    float o[8][4];
#pragma unroll
    for (int nf = 0; nf < 8; nf++)
#pragma unroll
        for (int r = 0; r < 4; r++) o[nf][r] = 0.f;
    float m0 = negInf(), m1 = negInf(), l0s = 0.f, l1s = 0.f;

    for (int kt = 0; kt < LSEQ / AKT; kt++) {
        __syncthreads();
        for (int i = tid; i < AKT * 16; i += 256) {
            int r = i >> 4, c4 = (i & 15) * 4;
            *(float4*)&Ks[r * KSS + c4] =
                tf32r4(*(const float4*)&kbase[((size_t)kt * AKT + r) * DIMN + c4]);
            *(float4*)&Vs[r * VSS + c4] =
                tf32r4(*(const float4*)&vbase[((size_t)kt * AKT + r) * DIMN + c4]);
        }
        __syncthreads();

        // ---- scores S = Q K^T ----
        float s[4][4];
#pragma unroll
        for (int nf = 0; nf < 4; nf++)
#pragma unroll
            for (int r = 0; r < 4; r++) s[nf][r] = 0.f;
#pragma unroll
        for (int kk = 0; kk < 8; kk++) {
#pragma unroll
            for (int nf = 0; nf < 4; nf++) {
                uint32_t bb[2];
                bb[0] = __float_as_uint(Ks[(nf * 8 + g) * KSS + kk * 8 + tig]);
                bb[1] = __float_as_uint(Ks[(nf * 8 + g) * KSS + kk * 8 + tig + 4]);
                mma_tf32(s[nf], aq[kk], bb);
            }
        }

        // ---- online softmax (rows g, g+8) ----
        float t0 = negInf(), t1 = negInf();
#pragma unroll
        for (int nf = 0; nf < 4; nf++) {
            t0 = fmaxf(t0, fmaxf(s[nf][0], s[nf][1]));
            t1 = fmaxf(t1, fmaxf(s[nf][2], s[nf][3]));
        }
#pragma unroll
        for (int off = 1; off < 4; off <<= 1) {
            t0 = fmaxf(t0, __shfl_xor_sync(0xffffffffu, t0, off));
            t1 = fmaxf(t1, __shfl_xor_sync(0xffffffffu, t1, off));
        }
        float mn0 = fmaxf(m0, t0), mn1 = fmaxf(m1, t1);
        float c0 = __expf(m0 - mn0), c1 = __expf(m1 - mn1);
        l0s *= c0; l1s *= c1;
#pragma unroll
        for (int nf = 0; nf < 8; nf++) {
            o[nf][0] *= c0; o[nf][1] *= c0;
            o[nf][2] *= c1; o[nf][3] *= c1;
        }
        float ls0 = 0.f, ls1 = 0.f;
#pragma unroll
        for (int nf = 0; nf < 4; nf++) {
            float p0 = __expf(s[nf][0] - mn0);
            float p1 = __expf(s[nf][1] - mn0);
            float p2 = __expf(s[nf][2] - mn1);
            float p3 = __expf(s[nf][3] - mn1);
            ls0 += p0 + p1; ls1 += p2 + p3;
            prow0[nf * 8 + 2 * tig]     = tf32r(p0);
            prow0[nf * 8 + 2 * tig + 1] = tf32r(p1);
            prow1[nf * 8 + 2 * tig]     = tf32r(p2);
            prow1[nf * 8 + 2 * tig + 1] = tf32r(p3);
        }
#pragma unroll
        for (int off = 1; off < 4; off <<= 1) {
            ls0 += __shfl_xor_sync(0xffffffffu, ls0, off);
            ls1 += __shfl_xor_sync(0xffffffffu, ls1, off);
        }
        l0s += ls0; l1s += ls1;
        m0 = mn0; m1 = mn1;
        __syncwarp();

        // ---- O += P V ----
#pragma unroll
        for (int kk = 0; kk < 4; kk++) {
            uint32_t ap[4];
            ap[0] = __float_as_uint(prow0[kk * 8 + tig]);
            ap[1] = __float_as_uint(prow1[kk * 8 + tig]);
            ap[2] = __float_as_uint(prow0[kk * 8 + tig + 4]);
            ap[3] = __float_as_uint(prow1[kk * 8 + tig + 4]);
#pragma unroll
            for (int nf = 0; nf < 8; nf++) {
                uint32_t bb[2];
                bb[0] = __float_as_uint(Vs[(kk * 8 + tig) * VSS + nf * 8 + g]);
                bb[1] = __float_as_uint(Vs[(kk * 8 + tig + 4) * VSS + nf * 8 + g]);
                mma_tf32(o[nf], ap, bb);
            }
        }
    }

    // ---- normalize + max-pool via staging, two 32-dim halves ----
    float inv0 = 1.f / l0s, inv1 = 1.f / l1s;
#pragma unroll
    for (int nf = 0; nf < 8; nf++) {
        o[nf][0] *= inv0; o[nf][1] *= inv0;
        o[nf][2] *= inv1; o[nf][3] *= inv1;
    }
#pragma unroll
    for (int half = 0; half < 2; half++) {
        __syncthreads();
#pragma unroll
        for (int nf2 = 0; nf2 < 4; nf2++) {
            int nf = half * 4 + nf2;
            prow0[nf2 * 8 + 2 * tig]     = o[nf][0];
            prow0[nf2 * 8 + 2 * tig + 1] = o[nf][1];
            prow1[nf2 * 8 + 2 * tig]     = o[nf][2];
            prow1[nf2 * 8 + 2 * tig + 1] = o[nf][3];
        }
        __syncthreads();
        if (tid < 32) {
            float mx = negInf();
            for (int r = 0; r < 128; r++) mx = fmaxf(mx, Ps[r * PSS + tid]);
            atomicMaxF(&g_a1[b * DIMN + h * HDN + half * 32 + tid], mx);
        }
    }
}

// ============================================================
// 4a) attn2 phase A: partial channel scores over one L-chunk.
// ============================================================
__global__ __launch_bounds__(320) void attn2_score_kernel() {
    __shared__ float s_a[8 * 5 * 64];
    __shared__ float s_b[8 * 5 * 64];

    const int d = threadIdx.x, s = threadIdx.y;
    const int tid = s * 64 + d;
    const int wh = blockIdx.x, lc = blockIdx.y;
    const int w = wh / HEADSN, h = wh % HEADSN;

    const float* qb = g_q + (size_t)w * SHOTN * LSEQ * DIMN + h * HDN;
    const float* kb = g_k + (size_t)w * SHOTN * LSEQ * DIMN + h * HDN;

    float acc[5] = {0.f, 0.f, 0.f, 0.f, 0.f};

    for (int l0 = 0; l0 < LPC; l0 += 8) {
        __syncthreads();
        for (int i = tid; i < 2560; i += 320) {
            int dd = i & 63, tt = (i >> 6) % 5, li = i / 320;
            size_t off = ((size_t)tt * LSEQ + lc * LPC + l0 + li) * DIMN + dd;
            s_a[i] = qb[off];
            s_b[i] = kb[off];
        }
        __syncthreads();
#pragma unroll
        for (int li = 0; li < 8; li++) {
            float qv = s_a[li * 320 + s * 64 + d];
#pragma unroll
            for (int t = 0; t < 5; t++)
                acc[t] += qv * s_b[li * 320 + t * 64 + d];
        }
    }

    float* dst = g_s2p + (((size_t)wh * LCH + lc) * HDN + d) * 25 + s * 5;
#pragma unroll
    for (int t = 0; t < 5; t++) dst[t] = acc[t];
}

// ============================================================
// 4b) attn2 phase B: ordered reduce + softmax -> pw
// ============================================================
__global__ __launch_bounds__(320) void attn2_softmax_kernel() {
    const int d = threadIdx.x, s = threadIdx.y;
    const int wh = blockIdx.x;

    float acc[5];
#pragma unroll
    for (int t = 0; t < 5; t++) {
        float v = 0.f;
#pragma unroll
        for (int c = 0; c < LCH; c++)
            v += g_s2p[(((size_t)wh * LCH + c) * HDN + d) * 25 + s * 5 + t];
        acc[t] = v * SCALE_F;
    }

    float mx = negInf();
#pragma unroll
    for (int t = 0; t < 5; t++) mx = fmaxf(mx, acc[t]);
    float pw[5], sum = 0.f;
#pragma unroll
    for (int t = 0; t < 5; t++) { pw[t] = __expf(acc[t] - mx); sum += pw[t]; }
    float inv = 1.f / sum;
#pragma unroll
    for (int t = 0; t < 5; t++)
        g_pw[((size_t)wh * HDN + d) * 25 + s * 5 + t] = pw[t] * inv;
}

// ============================================================
// 4c) attn2 phase C: weighted V + max-pool, atomicMax.
// ============================================================
__global__ __launch_bounds__(320) void attn2_apply_kernel() {
    __shared__ float s_v[8 * 5 * 64];

    const int d = threadIdx.x, s = threadIdx.y;
    const int tid = s * 64 + d;
    const int wh = blockIdx.x, lc = blockIdx.y;
    const int w = wh / HEADSN, h = wh % HEADSN;

    const float* vb = g_v + (size_t)w * SHOTN * LSEQ * DIMN + h * HDN;

    float pw[5];
#pragma unroll
    for (int t = 0; t < 5; t++)
        pw[t] = g_pw[((size_t)wh * HDN + d) * 25 + s * 5 + t];

    float amax = negInf();
    for (int l0 = 0; l0 < LPC; l0 += 8) {
        __syncthreads();
        for (int i = tid; i < 2560; i += 320) {
            int dd = i & 63, tt = (i >> 6) % 5, li = i / 320;
            s_v[i] = vb[((size_t)tt * LSEQ + lc * LPC + l0 + li) * DIMN + dd];
        }
        __syncthreads();
#pragma unroll
        for (int li = 0; li < 8; li++) {
            float val = 0.f;
#pragma unroll
            for (int t = 0; t < 5; t++)
                val += pw[t] * s_v[li * 320 + t * 64 + d];
            amax = fmaxf(amax, val);
        }
    }

    atomicMaxF(&g_a2[((size_t)w * SHOTN + s) * DIMN + h * HDN + d], amax);
}

// ============================================================
// 5) LayerNorm both branches + combine + tanh-dot with wp
// ============================================================
__device__ __forceinline__ float blockReduceSum256(float v, float* red) {
#pragma unroll
    for (int o = 16; o > 0; o >>= 1) v += __shfl_down_sync(0xffffffffu, v, o);
    __syncthreads();
    if ((threadIdx.x & 31) == 0) red[threadIdx.x >> 5] = v;
    __syncthreads();
    float tot = 0.f;
#pragma unroll
    for (int i = 0; i < 8; i++) tot += red[i];
    return tot;
}

__global__ __launch_bounds__(256) void ln_kernel(
    const float* __restrict__ gamma, const float* __restrict__ beta,
    const float* __restrict__ wp, const float* __restrict__ bp)
{
    __shared__ float red[8];
    const int row = blockIdx.x, tid = threadIdx.x;
    const float* r1 = g_a1 + row * DIMN;
    const float* r2 = g_a2 + row * DIMN;

    float s1 = 0, q1 = 0, s2 = 0, q2 = 0;
    for (int j = tid; j < DIMN; j += 256) {
        float x = r1[j]; s1 += x; q1 += x * x;
        float y = r2[j]; s2 += y; q2 += y * y;
    }
    s1 = blockReduceSum256(s1, red);
    q1 = blockReduceSum256(q1, red);
    s2 = blockReduceSum256(s2, red);
    q2 = blockReduceSum256(q2, red);

    const float invd = 1.f / DIMN;
    float m1 = s1 * invd, m2 = s2 * invd;
    float rs1 = rsqrtf(q1 * invd - m1 * m1 + 1e-5f);
    float rs2 = rsqrtf(q2 * invd - m2 * m2 + 1e-5f);

    float dotv = 0.f;
    for (int j = tid; j < DIMN; j += 256) {
        float g = gamma[j], bb = beta[j];
        float l1 = (r1[j] - m1) * rs1 * g + bb;
        float l2 = (r2[j] - m2) * rs2 * g + bb;
        float at = 0.5f * (l1 + l2);
        g_attn[row * DIMN + j] = at;
        dotv += tanhf(at) * wp[j];
    }
    dotv = blockReduceSum256(dotv, red);
    if (tid == 0) g_z[row] = dotv + bp[0];
}

// ============================================================
// 6) softmax over shots + weighted sum of attn -> c[w, dim]
// ============================================================
__global__ __launch_bounds__(256) void weight_kernel() {
    const int w = blockIdx.x, tid = threadIdx.x;
    float zz[5], mx = negInf();
#pragma unroll
    for (int t = 0; t < 5; t++) { zz[t] = g_z[w * 5 + t]; mx = fmaxf(mx, zz[t]); }
    float pw[5], sum = 0.f;
#pragma unroll
    for (int t = 0; t < 5; t++) { pw[t] = __expf(zz[t] - mx); sum += pw[t]; }
    float inv = 1.f / sum;
    for (int j = tid; j < DIMN; j += 256) {
        float acc = 0.f;
#pragma unroll
        for (int t = 0; t < 5; t++)
            acc += pw[t] * g_attn[((size_t)w * 5 + t) * DIMN + j];
        g_c[w * DIMN + j] = acc * inv;
    }
}

// ============================================================
// 7) out[w,j] = c[w,:] . Wo[j,:] + SHOT*bo[j]
// ============================================================
__global__ __launch_bounds__(256) void out_kernel(
    const float* __restrict__ Wo, const float* __restrict__ bo,
    float* __restrict__ out)
{
    const int w = blockIdx.y;
    const int warp = threadIdx.x >> 5, lane = threadIdx.x & 31;
    const int j = blockIdx.x * 8 + warp;
    const float* cr = g_c + w * DIMN;
    const float* wr = Wo + (size_t)j * DIMN;
    float s = 0.f;
    for (int kk = lane; kk < DIMN; kk += 32) s += cr[kk] * wr[kk];
#pragma unroll
    for (int o = 16; o > 0; o >>= 1) s += __shfl_down_sync(0xffffffffu, s, o);
    if (lane == 0) out[w * DIMN + j] = s + (float)SHOTN * bo[j];
}

// ============================================================
// launcher
// ============================================================
extern "C" void kernel_launch(void* const* d_in, const int* in_sizes, int n_in,
                              void* d_out, int out_size)
{
    const float* x     = (const float*)d_in[0];
    const float* Wq    = (const float*)d_in[1];
    const float* bq    = (const float*)d_in[2];
    const float* Wk    = (const float*)d_in[3];
    const float* bk    = (const float*)d_in[4];
    const float* Wv    = (const float*)d_in[5];
    const float* bv    = (const float*)d_in[6];
    const float* gamma = (const float*)d_in[7];
    const float* beta  = (const float*)d_in[8];
    const float* wp    = (const float*)d_in[9];
    const float* bp    = (const float*)d_in[10];
    const float* Wo    = (const float*)d_in[11];
    const float* bo    = (const float*)d_in[12];
    float* out = (float*)d_out;

    float *qp, *kp, *vp;
    cudaGetSymbolAddress((void**)&qp, g_q);
    cudaGetSymbolAddress((void**)&kp, g_k);
    cudaGetSymbolAddress((void**)&vp, g_v);

    gemm_tc_kernel<<<dim3(DIMN / 128, (NB * LSEQ) / 128, 3), 256>>>(
        x, Wq, Wk, Wv, bq, bk, bv, qp, kp, vp);

    init_kernel<<<(2 * NB * DIMN + 255) / 256, 256>>>();

    dim3 agrid(LSEQ / 128, HEADSN, NB);          // (4, 12, 25)
    attn1_kernel<<<agrid, 256>>>();

    attn2_score_kernel<<<dim3(WAYN * HEADSN, LCH), dim3(64, 5)>>>();
    attn2_softmax_kernel<<<WAYN * HEADSN, dim3(64, 5)>>>();
    attn2_apply_kernel<<<dim3(WAYN * HEADSN, LCH), dim3(64, 5)>>>();

    ln_kernel<<<NB, 256>>>(gamma, beta, wp, bp);
    weight_kernel<<<WAYN, 256>>>();
    out_kernel<<<dim3(DIMN / 8, WAYN), 256>>>(Wo, bo, out);
}

// round 14
// speedup vs baseline: 1.0060x; 1.0054x over previous
#include <cuda_runtime.h>
#include <cstdint>

// ============================================================
// ProtoMulHeadAttn  (WAY=5, SHOT=5, HEADS=12, DIM=768, L=512)
// Projections + attn1: mma.sync tf32, cvt done at staging.
// attn2: 3-phase parallel deterministic pipeline.
// ============================================================

#define WAYN   5
#define SHOTN  5
#define HEADSN 12
#define DIMN   768
#define LSEQ   512
#define HDN    64
#define NB     25            // WAY*SHOT
#define SCALE_F 0.125f       // 1/sqrt(64)
#define LCH    8             // attn2 L-chunks
#define LPC    (LSEQ / LCH)  // 64 tokens per chunk

// ---------------- scratch (static device memory; no allocs) ----------------
__device__ float g_q[NB * LSEQ * DIMN];
__device__ float g_k[NB * LSEQ * DIMN];
__device__ float g_v[NB * LSEQ * DIMN];
__device__ float g_a1[NB * DIMN];
__device__ float g_a2[NB * DIMN];
__device__ float g_attn[NB * DIMN];
__device__ float g_z[NB];
__device__ float g_c[WAYN * DIMN];
__device__ float g_s2p[WAYN * HEADSN * LCH * HDN * SHOTN * SHOTN];
__device__ float g_pw[WAYN * HEADSN * HDN * SHOTN * SHOTN];

__device__ __forceinline__ float negInf() { return __int_as_float(0xff800000); }

__device__ __forceinline__ void atomicMaxF(float* addr, float val) {
    int* ia = (int*)addr;
    int old = *ia;
    while (__int_as_float(old) < val) {
        int prev = atomicCAS(ia, old, __float_as_int(val));
        if (prev == old) break;
        old = prev;
    }
}

// ---------------- tf32 mma helpers ----------------
__device__ __forceinline__ uint32_t cvt_tf32(float f) {
    uint32_t u;
    asm("cvt.rna.tf32.f32 %0, %1;" : "=r"(u) : "f"(f));
    return u;
}
// round-to-tf32, result as float bit pattern (for smem staging)
__device__ __forceinline__ float tf32r(float f) {
    return __uint_as_float(cvt_tf32(f));
}
__device__ __forceinline__ float4 tf32r4(float4 v) {
    float4 r;
    r.x = tf32r(v.x); r.y = tf32r(v.y); r.z = tf32r(v.z); r.w = tf32r(v.w);
    return r;
}

__device__ __forceinline__ void mma_tf32(float* c, const uint32_t* a, const uint32_t* b) {
    asm volatile(
        "mma.sync.aligned.m16n8k8.row.col.f32.tf32.tf32.f32 "
        "{%0,%1,%2,%3}, {%4,%5,%6,%7}, {%8,%9}, {%0,%1,%2,%3};"
        : "+f"(c[0]), "+f"(c[1]), "+f"(c[2]), "+f"(c[3])
        : "r"(a[0]), "r"(a[1]), "r"(a[2]), "r"(a[3]),
          "r"(b[0]), "r"(b[1]));
}

// ============================================================
// 1) Projection GEMM via tf32 mma.sync; smem holds pre-rounded
//    tf32 values (cvt at staging, fragments are plain LDS).
// ============================================================
#define KC   16
#define PADK 20
#define NKIT (DIMN / KC)     // 48

__global__ __launch_bounds__(256) void gemm_tc_kernel(
    const float* __restrict__ A,
    const float* __restrict__ W0, const float* __restrict__ W1, const float* __restrict__ W2,
    const float* __restrict__ b0, const float* __restrict__ b1, const float* __restrict__ b2,
    float* __restrict__ o0, float* __restrict__ o1, float* __restrict__ o2)
{
    __shared__ __align__(16) float As[2][128 * PADK];
    __shared__ __align__(16) float Bs[2][128 * PADK];

    const int tid = threadIdx.x;
    const int wid = tid >> 5, lane = tid & 31;
    const int g = lane >> 2, tig = lane & 3;
    const int wm = (wid >> 2) * 64;
    const int wn = (wid & 3) * 32;
    const int n0 = blockIdx.x * 128;
    const int m0 = blockIdx.y * 128;
    const int which = blockIdx.z;
    const float* W    = (which == 0) ? W0 : (which == 1) ? W1 : W2;
    const float* bias = (which == 0) ? b0 : (which == 1) ? b1 : b2;
    float* Cout       = (which == 0) ? o0 : (which == 1) ? o1 : o2;

    const float* Ag = A + (size_t)m0 * DIMN;
    const float* Wg = W + (size_t)n0 * DIMN;

    float c[4][4][4];
#pragma unroll
    for (int mf = 0; mf < 4; mf++)
#pragma unroll
        for (int nf = 0; nf < 4; nf++)
#pragma unroll
            for (int r = 0; r < 4; r++) c[mf][nf][r] = 0.f;

#pragma unroll
    for (int u = 0; u < 2; u++) {
        int idx = tid + u * 256;
        int r = idx >> 2, c4 = (idx & 3) << 2;
        *(float4*)&As[0][r * PADK + c4] = tf32r4(*(const float4*)&Ag[(size_t)r * DIMN + c4]);
        *(float4*)&Bs[0][r * PADK + c4] = tf32r4(*(const float4*)&Wg[(size_t)r * DIMN + c4]);
    }
    __syncthreads();

    float4 pa[2], pb[2];
    for (int it = 0; it < NKIT; it++) {
        const int s = it & 1;
        if (it + 1 < NKIT) {
            const int kn = (it + 1) * KC;
#pragma unroll
            for (int u = 0; u < 2; u++) {
                int idx = tid + u * 256;
                int r = idx >> 2, c4 = (idx & 3) << 2;
                pa[u] = *(const float4*)&Ag[(size_t)r * DIMN + kn + c4];
                pb[u] = *(const float4*)&Wg[(size_t)r * DIMN + kn + c4];
            }
        }

#pragma unroll
        for (int ks = 0; ks < 2; ks++) {
            uint32_t af[4][4], bf[4][2];
#pragma unroll
            for (int mf = 0; mf < 4; mf++) {
                int rb = (wm + mf * 16 + g) * PADK + ks * 8 + tig;
                af[mf][0] = __float_as_uint(As[s][rb]);
                af[mf][1] = __float_as_uint(As[s][rb + 8 * PADK]);
                af[mf][2] = __float_as_uint(As[s][rb + 4]);
                af[mf][3] = __float_as_uint(As[s][rb + 8 * PADK + 4]);
            }
#pragma unroll
            for (int nf = 0; nf < 4; nf++) {
                int rb = (wn + nf * 8 + g) * PADK + ks * 8 + tig;
                bf[nf][0] = __float_as_uint(Bs[s][rb]);
                bf[nf][1] = __float_as_uint(Bs[s][rb + 4]);
            }
#pragma unroll
            for (int mf = 0; mf < 4; mf++)
#pragma unroll
                for (int nf = 0; nf < 4; nf++)
                    mma_tf32(c[mf][nf], af[mf], bf[nf]);
        }

        if (it + 1 < NKIT) {
            const int sn = s ^ 1;
#pragma unroll
            for (int u = 0; u < 2; u++) {
                int idx = tid + u * 256;
                int r = idx >> 2, c4 = (idx & 3) << 2;
                *(float4*)&As[sn][r * PADK + c4] = tf32r4(pa[u]);
                *(float4*)&Bs[sn][r * PADK + c4] = tf32r4(pb[u]);
            }
        }
        __syncthreads();
    }

#pragma unroll
    for (int mf = 0; mf < 4; mf++) {
        int row = m0 + wm + mf * 16 + g;
#pragma unroll
        for (int nf = 0; nf < 4; nf++) {
            int col = n0 + wn + nf * 8 + tig * 2;
            float bx = bias[col], by = bias[col + 1];
            float2 v0 = {c[mf][nf][0] + bx, c[mf][nf][1] + by};
            float2 v1 = {c[mf][nf][2] + bx, c[mf][nf][3] + by};
            *(float2*)&Cout[(size_t)row * DIMN + col] = v0;
            *(float2*)&Cout[(size_t)(row + 8) * DIMN + col] = v1;
        }
    }
}

// ============================================================
// 2) init a1/a2 to -inf (atomicMax targets)
// ============================================================
__global__ void init_kernel() {
    int i = blockIdx.x * 256 + threadIdx.x;
    if (i < NB * DIMN) g_a1[i] = negInf();
    else if (i < 2 * NB * DIMN) g_a2[i - NB * DIMN] = negInf();
}

// ============================================================
// 3) Branch-1 flash attention via tf32 mma + fused max-pool.
//    K/V/P pre-rounded to tf32 at their smem writes.
// ============================================================
#define AKT  32
#define PSS  36
#define KSS  68
#define VSS  72

__global__ __launch_bounds__(256) void attn1_kernel() {
    __shared__ __align__(16) float Ps[128 * PSS];
    __shared__ __align__(16) float Ks[AKT * KSS];
    __shared__ __align__(16) float Vs[AKT * VSS];

    const int tid = threadIdx.x;
    const int wid = tid >> 5, lane = tid & 31;
    const int g = lane >> 2, tig = lane & 3;
    const int qt = blockIdx.x, h = blockIdx.y, b = blockIdx.z;

    const float* qbase = g_q + ((size_t)b * LSEQ + qt * 128) * DIMN + h * HDN;
    const float* kbase = g_k + (size_t)b * LSEQ * DIMN + h * HDN;
    const float* vbase = g_v + (size_t)b * LSEQ * DIMN + h * HDN;

    float* prow0 = &Ps[(wid * 16 + g) * PSS];
    float* prow1 = &Ps[(wid * 16 + g + 8) * PSS];

    // ---- Q fragments (persistent), staged in two 32-col halves ----
    uint32_t aq[8][4];
#pragma unroll
    for (int half = 0; half < 2; half++) {
        __syncthreads();
        for (int i = tid; i < 128 * 32; i += 256) {
            int r = i >> 5, d = i & 31;
            Ps[r * PSS + d] = qbase[(size_t)r * DIMN + half * 32 + d] * SCALE_F;
        }
        __syncthreads();
#pragma unroll
        for (int k2 = 0; k2 < 4; k2++) {
            int kk = half * 4 + k2;
            aq[kk][0] = cvt_tf32(prow0[k2 * 8 + tig]);
            aq[kk][1] = cvt_tf32(prow1[k2 * 8 + tig]);
            aq[kk][2] = cvt_tf32(prow0[k2 * 8 + tig + 4]);
            aq[kk][3] = cvt_tf32(prow1[k2 * 8 + tig + 4]);
        }
    }

    float o[8][4];
#pragma unroll
    for (int nf = 0; nf < 8; nf++)
#pragma unroll
        for (int r = 0; r < 4; r++) o[nf][r] = 0.f;
    float m0 = negInf(), m1 = negInf(), l0s = 0.f, l1s = 0.f;

    for (int kt = 0; kt < LSEQ / AKT; kt++) {
        __syncthreads();
        for (int i = tid; i < AKT * 16; i += 256) {
            int r = i >> 4, c4 = (i & 15) * 4;
            *(float4*)&Ks[r * KSS + c4] =
                tf32r4(*(const float4*)&kbase[((size_t)kt * AKT + r) * DIMN + c4]);
            *(float4*)&Vs[r * VSS + c4] =
                tf32r4(*(const float4*)&vbase[((size_t)kt * AKT + r) * DIMN + c4]);
        }
        __syncthreads();

        // ---- scores S = Q K^T ----
        float s[4][4];
#pragma unroll
        for (int nf = 0; nf < 4; nf++)
#pragma unroll
            for (int r = 0; r < 4; r++) s[nf][r] = 0.f;
#pragma unroll
        for (int kk = 0; kk < 8; kk++) {
#pragma unroll
            for (int nf = 0; nf < 4; nf++) {
                uint32_t bb[2];
                bb[0] = __float_as_uint(Ks[(nf * 8 + g) * KSS + kk * 8 + tig]);
                bb[1] = __float_as_uint(Ks[(nf * 8 + g) * KSS + kk * 8 + tig + 4]);
                mma_tf32(s[nf], aq[kk], bb);
            }
        }

        // ---- online softmax (rows g, g+8) ----
        float t0 = negInf(), t1 = negInf();
#pragma unroll
        for (int nf = 0; nf < 4; nf++) {
            t0 = fmaxf(t0, fmaxf(s[nf][0], s[nf][1]));
            t1 = fmaxf(t1, fmaxf(s[nf][2], s[nf][3]));
        }
#pragma unroll
        for (int off = 1; off < 4; off <<= 1) {
            t0 = fmaxf(t0, __shfl_xor_sync(0xffffffffu, t0, off));
            t1 = fmaxf(t1, __shfl_xor_sync(0xffffffffu, t1, off));
        }
        float mn0 = fmaxf(m0, t0), mn1 = fmaxf(m1, t1);
        float c0 = __expf(m0 - mn0), c1 = __expf(m1 - mn1);
        l0s *= c0; l1s *= c1;
#pragma unroll
        for (int nf = 0; nf < 8; nf++) {
            o[nf][0] *= c0; o[nf][1] *= c0;
            o[nf][2] *= c1; o[nf][3] *= c1;
        }
        float ls0 = 0.f, ls1 = 0.f;
#pragma unroll
        for (int nf = 0; nf < 4; nf++) {
            float p0 = __expf(s[nf][0] - mn0);
            float p1 = __expf(s[nf][1] - mn0);
            float p2 = __expf(s[nf][2] - mn1);
            float p3 = __expf(s[nf][3] - mn1);
            ls0 += p0 + p1; ls1 += p2 + p3;
            prow0[nf * 8 + 2 * tig]     = tf32r(p0);
            prow0[nf * 8 + 2 * tig + 1] = tf32r(p1);
            prow1[nf * 8 + 2 * tig]     = tf32r(p2);
            prow1[nf * 8 + 2 * tig + 1] = tf32r(p3);
        }
#pragma unroll
        for (int off = 1; off < 4; off <<= 1) {
            ls0 += __shfl_xor_sync(0xffffffffu, ls0, off);
            ls1 += __shfl_xor_sync(0xffffffffu, ls1, off);
        }
        l0s += ls0; l1s += ls1;
        m0 = mn0; m1 = mn1;
        __syncwarp();

        // ---- O += P V ----
#pragma unroll
        for (int kk = 0; kk < 4; kk++) {
            uint32_t ap[4];
            ap[0] = __float_as_uint(prow0[kk * 8 + tig]);
            ap[1] = __float_as_uint(prow1[kk * 8 + tig]);
            ap[2] = __float_as_uint(prow0[kk * 8 + tig + 4]);
            ap[3] = __float_as_uint(prow1[kk * 8 + tig + 4]);
#pragma unroll
            for (int nf = 0; nf < 8; nf++) {
                uint32_t bb[2];
                bb[0] = __float_as_uint(Vs[(kk * 8 + tig) * VSS + nf * 8 + g]);
                bb[1] = __float_as_uint(Vs[(kk * 8 + tig + 4) * VSS + nf * 8 + g]);
                mma_tf32(o[nf], ap, bb);
            }
        }
    }

    // ---- normalize + max-pool via staging, two 32-dim halves ----
    float inv0 = 1.f / l0s, inv1 = 1.f / l1s;
#pragma unroll
    for (int nf = 0; nf < 8; nf++) {
        o[nf][0] *= inv0; o[nf][1] *= inv0;
        o[nf][2] *= inv1; o[nf][3] *= inv1;
    }
#pragma unroll
    for (int half = 0; half < 2; half++) {
        __syncthreads();
#pragma unroll
        for (int nf2 = 0; nf2 < 4; nf2++) {
            int nf = half * 4 + nf2;
            prow0[nf2 * 8 + 2 * tig]     = o[nf][0];
            prow0[nf2 * 8 + 2 * tig + 1] = o[nf][1];
            prow1[nf2 * 8 + 2 * tig]     = o[nf][2];
            prow1[nf2 * 8 + 2 * tig + 1] = o[nf][3];
        }
        __syncthreads();
        if (tid < 32) {
            float mx = negInf();
            for (int r = 0; r < 128; r++) mx = fmaxf(mx, Ps[r * PSS + tid]);
            atomicMaxF(&g_a1[b * DIMN + h * HDN + half * 32 + tid], mx);
        }
    }
}

// ============================================================
// 4a) attn2 phase A: partial channel scores over one L-chunk.
// ============================================================
__global__ __launch_bounds__(320) void attn2_score_kernel() {
    __shared__ float s_a[8 * 5 * 64];
    __shared__ float s_b[8 * 5 * 64];

    const int d = threadIdx.x, s = threadIdx.y;
    const int tid = s * 64 + d;
    const int wh = blockIdx.x, lc = blockIdx.y;
    const int w = wh / HEADSN, h = wh % HEADSN;

    const float* qb = g_q + (size_t)w * SHOTN * LSEQ * DIMN + h * HDN;
    const float* kb = g_k + (size_t)w * SHOTN * LSEQ * DIMN + h * HDN;

    float acc[5] = {0.f, 0.f, 0.f, 0.f, 0.f};

    for (int l0 = 0; l0 < LPC; l0 += 8) {
        __syncthreads();
        for (int i = tid; i < 2560; i += 320) {
            int dd = i & 63, tt = (i >> 6) % 5, li = i / 320;
            size_t off = ((size_t)tt * LSEQ + lc * LPC + l0 + li) * DIMN + dd;
            s_a[i] = qb[off];
            s_b[i] = kb[off];
        }
        __syncthreads();
#pragma unroll
        for (int li = 0; li < 8; li++) {
            float qv = s_a[li * 320 + s * 64 + d];
#pragma unroll
            for (int t = 0; t < 5; t++)
                acc[t] += qv * s_b[li * 320 + t * 64 + d];
        }
    }

    float* dst = g_s2p + (((size_t)wh * LCH + lc) * HDN + d) * 25 + s * 5;
#pragma unroll
    for (int t = 0; t < 5; t++) dst[t] = acc[t];
}

// ============================================================
// 4b) attn2 phase B: ordered reduce + softmax -> pw
// ============================================================
__global__ __launch_bounds__(320) void attn2_softmax_kernel() {
    const int d = threadIdx.x, s = threadIdx.y;
    const int wh = blockIdx.x;

    float acc[5];
#pragma unroll
    for (int t = 0; t < 5; t++) {
        float v = 0.f;
#pragma unroll
        for (int c = 0; c < LCH; c++)
            v += g_s2p[(((size_t)wh * LCH + c) * HDN + d) * 25 + s * 5 + t];
        acc[t] = v * SCALE_F;
    }

    float mx = negInf();
#pragma unroll
    for (int t = 0; t < 5; t++) mx = fmaxf(mx, acc[t]);
    float pw[5], sum = 0.f;
#pragma unroll
    for (int t = 0; t < 5; t++) { pw[t] = __expf(acc[t] - mx); sum += pw[t]; }
    float inv = 1.f / sum;
#pragma unroll
    for (int t = 0; t < 5; t++)
        g_pw[((size_t)wh * HDN + d) * 25 + s * 5 + t] = pw[t] * inv;
}

// ============================================================
// 4c) attn2 phase C: weighted V + max-pool, atomicMax.
// ============================================================
__global__ __launch_bounds__(320) void attn2_apply_kernel() {
    __shared__ float s_v[8 * 5 * 64];

    const int d = threadIdx.x, s = threadIdx.y;
    const int tid = s * 64 + d;
    const int wh = blockIdx.x, lc = blockIdx.y;
    const int w = wh / HEADSN, h = wh % HEADSN;

    const float* vb = g_v + (size_t)w * SHOTN * LSEQ * DIMN + h * HDN;

    float pw[5];
#pragma unroll
    for (int t = 0; t < 5; t++)
        pw[t] = g_pw[((size_t)wh * HDN + d) * 25 + s * 5 + t];

    float amax = negInf();
    for (int l0 = 0; l0 < LPC; l0 += 8) {
        __syncthreads();
        for (int i = tid; i < 2560; i += 320) {
            int dd = i & 63, tt = (i >> 6) % 5, li = i / 320;
            s_v[i] = vb[((size_t)tt * LSEQ + lc * LPC + l0 + li) * DIMN + dd];
        }
        __syncthreads();
#pragma unroll
        for (int li = 0; li < 8; li++) {
            float val = 0.f;
#pragma unroll
            for (int t = 0; t < 5; t++)
                val += pw[t] * s_v[li * 320 + t * 64 + d];
            amax = fmaxf(amax, val);
        }
    }

    atomicMaxF(&g_a2[((size_t)w * SHOTN + s) * DIMN + h * HDN + d], amax);
}

// ============================================================
// 5) LayerNorm both branches + combine + tanh-dot with wp
// ============================================================
__device__ __forceinline__ float blockReduceSum256(float v, float* red) {
#pragma unroll
    for (int o = 16; o > 0; o >>= 1) v += __shfl_down_sync(0xffffffffu, v, o);
    __syncthreads();
    if ((threadIdx.x & 31) == 0) red[threadIdx.x >> 5] = v;
    __syncthreads();
    float tot = 0.f;
#pragma unroll
    for (int i = 0; i < 8; i++) tot += red[i];
    return tot;
}

__global__ __launch_bounds__(256) void ln_kernel(
    const float* __restrict__ gamma, const float* __restrict__ beta,
    const float* __restrict__ wp, const float* __restrict__ bp)
{
    __shared__ float red[8];
    const int row = blockIdx.x, tid = threadIdx.x;
    const float* r1 = g_a1 + row * DIMN;
    const float* r2 = g_a2 + row * DIMN;

    float s1 = 0, q1 = 0, s2 = 0, q2 = 0;
    for (int j = tid; j < DIMN; j += 256) {
        float x = r1[j]; s1 += x; q1 += x * x;
        float y = r2[j]; s2 += y; q2 += y * y;
    }
    s1 = blockReduceSum256(s1, red);
    q1 = blockReduceSum256(q1, red);
    s2 = blockReduceSum256(s2, red);
    q2 = blockReduceSum256(q2, red);

    const float invd = 1.f / DIMN;
    float m1 = s1 * invd, m2 = s2 * invd;
    float rs1 = rsqrtf(q1 * invd - m1 * m1 + 1e-5f);
    float rs2 = rsqrtf(q2 * invd - m2 * m2 + 1e-5f);

    float dotv = 0.f;
    for (int j = tid; j < DIMN; j += 256) {
        float g = gamma[j], bb = beta[j];
        float l1 = (r1[j] - m1) * rs1 * g + bb;
        float l2 = (r2[j] - m2) * rs2 * g + bb;
        float at = 0.5f * (l1 + l2);
        g_attn[row * DIMN + j] = at;
        dotv += tanhf(at) * wp[j];
    }
    dotv = blockReduceSum256(dotv, red);
    if (tid == 0) g_z[row] = dotv + bp[0];
}

// ============================================================
// 6) softmax over shots + weighted sum of attn -> c[w, dim]
// ============================================================
__global__ __launch_bounds__(256) void weight_kernel() {
    const int w = blockIdx.x, tid = threadIdx.x;
    float zz[5], mx = negInf();
#pragma unroll
    for (int t = 0; t < 5; t++) { zz[t] = g_z[w * 5 + t]; mx = fmaxf(mx, zz[t]); }
    float pw[5], sum = 0.f;
#pragma unroll
    for (int t = 0; t < 5; t++) { pw[t] = __expf(zz[t] - mx); sum += pw[t]; }
    float inv = 1.f / sum;
    for (int j = tid; j < DIMN; j += 256) {
        float acc = 0.f;
#pragma unroll
        for (int t = 0; t < 5; t++)
            acc += pw[t] * g_attn[((size_t)w * 5 + t) * DIMN + j];
        g_c[w * DIMN + j] = acc * inv;
    }
}

// ============================================================
// 7) out[w,j] = c[w,:] . Wo[j,:] + SHOT*bo[j]
// ============================================================
__global__ __launch_bounds__(256) void out_kernel(
    const float* __restrict__ Wo, const float* __restrict__ bo,
    float* __restrict__ out)
{
    const int w = blockIdx.y;
    const int warp = threadIdx.x >> 5, lane = threadIdx.x & 31;
    const int j = blockIdx.x * 8 + warp;
    const float* cr = g_c + w * DIMN;
    const float* wr = Wo + (size_t)j * DIMN;
    float s = 0.f;
    for (int kk = lane; kk < DIMN; kk += 32) s += cr[kk] * wr[kk];
#pragma unroll
    for (int o = 16; o > 0; o >>= 1) s += __shfl_down_sync(0xffffffffu, s, o);
    if (lane == 0) out[w * DIMN + j] = s + (float)SHOTN * bo[j];
}

// ============================================================
// launcher
// ============================================================
extern "C" void kernel_launch(void* const* d_in, const int* in_sizes, int n_in,
                              void* d_out, int out_size)
{
    const float* x     = (const float*)d_in[0];
    const float* Wq    = (const float*)d_in[1];
    const float* bq    = (const float*)d_in[2];
    const float* Wk    = (const float*)d_in[3];
    const float* bk    = (const float*)d_in[4];
    const float* Wv    = (const float*)d_in[5];
    const float* bv    = (const float*)d_in[6];
    const float* gamma = (const float*)d_in[7];
    const float* beta  = (const float*)d_in[8];
    const float* wp    = (const float*)d_in[9];
    const float* bp    = (const float*)d_in[10];
    const float* Wo    = (const float*)d_in[11];
    const float* bo    = (const float*)d_in[12];
    float* out = (float*)d_out;

    float *qp, *kp, *vp;
    cudaGetSymbolAddress((void**)&qp, g_q);
    cudaGetSymbolAddress((void**)&kp, g_k);
    cudaGetSymbolAddress((void**)&vp, g_v);

    gemm_tc_kernel<<<dim3(DIMN / 128, (NB * LSEQ) / 128, 3), 256>>>(
        x, Wq, Wk, Wv, bq, bk, bv, qp, kp, vp);

    init_kernel<<<(2 * NB * DIMN + 255) / 256, 256>>>();

    dim3 agrid(LSEQ / 128, HEADSN, NB);          // (4, 12, 25)
    attn1_kernel<<<agrid, 256>>>();

    attn2_score_kernel<<<dim3(WAYN * HEADSN, LCH), dim3(64, 5)>>>();
    attn2_softmax_kernel<<<WAYN * HEADSN, dim3(64, 5)>>>();
    attn2_apply_kernel<<<dim3(WAYN * HEADSN, LCH), dim3(64, 5)>>>();

    ln_kernel<<<NB, 256>>>(gamma, beta, wp, bp);
    weight_kernel<<<WAYN, 256>>>();
    out_kernel<<<dim3(DIMN / 8, WAYN), 256>>>(Wo, bo, out);
}

// round 15
// speedup vs baseline: 1.0073x; 1.0013x over previous
#include <cuda_runtime.h>
#include <cstdint>

// ============================================================
// ProtoMulHeadAttn  (WAY=5, SHOT=5, HEADS=12, DIM=768, L=512)
// Projections + attn1: mma.sync tf32, cvt done at staging.
// attn2: 3-phase parallel deterministic pipeline.
// ============================================================

#define WAYN   5
#define SHOTN  5
#define HEADSN 12
#define DIMN   768
#define LSEQ   512
#define HDN    64
#define NB     25            // WAY*SHOT
#define SCALE_F 0.125f       // 1/sqrt(64)
#define LCH    8             // attn2 L-chunks
#define LPC    (LSEQ / LCH)  // 64 tokens per chunk

// ---------------- scratch (static device memory; no allocs) ----------------
__device__ float g_q[NB * LSEQ * DIMN];
__device__ float g_k[NB * LSEQ * DIMN];
__device__ float g_v[NB * LSEQ * DIMN];
__device__ float g_a1[NB * DIMN];
__device__ float g_a2[NB * DIMN];
__device__ float g_attn[NB * DIMN];
__device__ float g_z[NB];
__device__ float g_c[WAYN * DIMN];
__device__ float g_s2p[WAYN * HEADSN * LCH * HDN * SHOTN * SHOTN];
__device__ float g_pw[WAYN * HEADSN * HDN * SHOTN * SHOTN];

__device__ __forceinline__ float negInf() { return __int_as_float(0xff800000); }

__device__ __forceinline__ void atomicMaxF(float* addr, float val) {
    int* ia = (int*)addr;
    int old = *ia;
    while (__int_as_float(old) < val) {
        int prev = atomicCAS(ia, old, __float_as_int(val));
        if (prev == old) break;
        old = prev;
    }
}

// ---------------- tf32 mma helpers ----------------
__device__ __forceinline__ uint32_t cvt_tf32(float f) {
    uint32_t u;
    asm("cvt.rna.tf32.f32 %0, %1;" : "=r"(u) : "f"(f));
    return u;
}
// round-to-tf32, result as float bit pattern (for smem staging)
__device__ __forceinline__ float tf32r(float f) {
    return __uint_as_float(cvt_tf32(f));
}
__device__ __forceinline__ float4 tf32r4(float4 v) {
    float4 r;
    r.x = tf32r(v.x); r.y = tf32r(v.y); r.z = tf32r(v.z); r.w = tf32r(v.w);
    return r;
}

__device__ __forceinline__ void mma_tf32(float* c, const uint32_t* a, const uint32_t* b) {
    asm volatile(
        "mma.sync.aligned.m16n8k8.row.col.f32.tf32.tf32.f32 "
        "{%0,%1,%2,%3}, {%4,%5,%6,%7}, {%8,%9}, {%0,%1,%2,%3};"
        : "+f"(c[0]), "+f"(c[1]), "+f"(c[2]), "+f"(c[3])
        : "r"(a[0]), "r"(a[1]), "r"(a[2]), "r"(a[3]),
          "r"(b[0]), "r"(b[1]));
}

// ============================================================
// 1) Projection GEMM via tf32 mma.sync; smem holds pre-rounded
//    tf32 values (cvt at staging, fragments are plain LDS).
// ============================================================
#define KC   16
#define PADK 20
#define NKIT (DIMN / KC)     // 48

__global__ __launch_bounds__(256) void gemm_tc_kernel(
    const float* __restrict__ A,
    const float* __restrict__ W0, const float* __restrict__ W1, const float* __restrict__ W2,
    const float* __restrict__ b0, const float* __restrict__ b1, const float* __restrict__ b2,
    float* __restrict__ o0, float* __restrict__ o1, float* __restrict__ o2)
{
    __shared__ __align__(16) float As[2][128 * PADK];
    __shared__ __align__(16) float Bs[2][128 * PADK];

    const int tid = threadIdx.x;
    const int wid = tid >> 5, lane = tid & 31;
    const int g = lane >> 2, tig = lane & 3;
    const int wm = (wid >> 2) * 64;
    const int wn = (wid & 3) * 32;
    const int n0 = blockIdx.x * 128;
    const int m0 = blockIdx.y * 128;
    const int which = blockIdx.z;
    const float* W    = (which == 0) ? W0 : (which == 1) ? W1 : W2;
    const float* bias = (which == 0) ? b0 : (which == 1) ? b1 : b2;
    float* Cout       = (which == 0) ? o0 : (which == 1) ? o1 : o2;

    const float* Ag = A + (size_t)m0 * DIMN;
    const float* Wg = W + (size_t)n0 * DIMN;

    float c[4][4][4];
#pragma unroll
    for (int mf = 0; mf < 4; mf++)
#pragma unroll
        for (int nf = 0; nf < 4; nf++)
#pragma unroll
            for (int r = 0; r < 4; r++) c[mf][nf][r] = 0.f;

#pragma unroll
    for (int u = 0; u < 2; u++) {
        int idx = tid + u * 256;
        int r = idx >> 2, c4 = (idx & 3) << 2;
        *(float4*)&As[0][r * PADK + c4] = tf32r4(*(const float4*)&Ag[(size_t)r * DIMN + c4]);
        *(float4*)&Bs[0][r * PADK + c4] = tf32r4(*(const float4*)&Wg[(size_t)r * DIMN + c4]);
    }
    __syncthreads();

    float4 pa[2], pb[2];
    for (int it = 0; it < NKIT; it++) {
        const int s = it & 1;
        if (it + 1 < NKIT) {
            const int kn = (it + 1) * KC;
#pragma unroll
            for (int u = 0; u < 2; u++) {
                int idx = tid + u * 256;
                int r = idx >> 2, c4 = (idx & 3) << 2;
                pa[u] = *(const float4*)&Ag[(size_t)r * DIMN + kn + c4];
                pb[u] = *(const float4*)&Wg[(size_t)r * DIMN + kn + c4];
            }
        }

#pragma unroll
        for (int ks = 0; ks < 2; ks++) {
            uint32_t af[4][4], bf[4][2];
#pragma unroll
            for (int mf = 0; mf < 4; mf++) {
                int rb = (wm + mf * 16 + g) * PADK + ks * 8 + tig;
                af[mf][0] = __float_as_uint(As[s][rb]);
                af[mf][1] = __float_as_uint(As[s][rb + 8 * PADK]);
                af[mf][2] = __float_as_uint(As[s][rb + 4]);
                af[mf][3] = __float_as_uint(As[s][rb + 8 * PADK + 4]);
            }
#pragma unroll
            for (int nf = 0; nf < 4; nf++) {
                int rb = (wn + nf * 8 + g) * PADK + ks * 8 + tig;
                bf[nf][0] = __float_as_uint(Bs[s][rb]);
                bf[nf][1] = __float_as_uint(Bs[s][rb + 4]);
            }
#pragma unroll
            for (int mf = 0; mf < 4; mf++)
#pragma unroll
                for (int nf = 0; nf < 4; nf++)
                    mma_tf32(c[mf][nf], af[mf], bf[nf]);
        }

        if (it + 1 < NKIT) {
            const int sn = s ^ 1;
#pragma unroll
            for (int u = 0; u < 2; u++) {
                int idx = tid + u * 256;
                int r = idx >> 2, c4 = (idx & 3) << 2;
                *(float4*)&As[sn][r * PADK + c4] = tf32r4(pa[u]);
                *(float4*)&Bs[sn][r * PADK + c4] = tf32r4(pb[u]);
            }
        }
        __syncthreads();
    }

#pragma unroll
    for (int mf = 0; mf < 4; mf++) {
        int row = m0 + wm + mf * 16 + g;
#pragma unroll
        for (int nf = 0; nf < 4; nf++) {
            int col = n0 + wn + nf * 8 + tig * 2;
            float bx = bias[col], by = bias[col + 1];
            float2 v0 = {c[mf][nf][0] + bx, c[mf][nf][1] + by};
            float2 v1 = {c[mf][nf][2] + bx, c[mf][nf][3] + by};
            *(float2*)&Cout[(size_t)row * DIMN + col] = v0;
            *(float2*)&Cout[(size_t)(row + 8) * DIMN + col] = v1;
        }
    }
}

// ============================================================
// 2) init a1/a2 to -inf (atomicMax targets)
// ============================================================
__global__ void init_kernel() {
    int i = blockIdx.x * 256 + threadIdx.x;
    if (i < NB * DIMN) g_a1[i] = negInf();
    else if (i < 2 * NB * DIMN) g_a2[i - NB * DIMN] = negInf();
}

// ============================================================
// 3) Branch-1 flash attention via tf32 mma + fused max-pool.
//    K/V/P pre-rounded to tf32 at their smem writes.
// ============================================================
#define AKT  32
#define PSS  36
#define KSS  68
#define VSS  72

__global__ __launch_bounds__(256) void attn1_kernel() {
    __shared__ __align__(16) float Ps[128 * PSS];
    __shared__ __align__(16) float Ks[AKT * KSS];
    __shared__ __align__(16) float Vs[AKT * VSS];

    const int tid = threadIdx.x;
    const int wid = tid >> 5, lane = tid & 31;
    const int g = lane >> 2, tig = lane & 3;
    const int qt = blockIdx.x, h = blockIdx.y, b = blockIdx.z;

    const float* qbase = g_q + ((size_t)b * LSEQ + qt * 128) * DIMN + h * HDN;
    const float* kbase = g_k + (size_t)b * LSEQ * DIMN + h * HDN;
    const float* vbase = g_v + (size_t)b * LSEQ * DIMN + h * HDN;

    float* prow0 = &Ps[(wid * 16 + g) * PSS];
    float* prow1 = &Ps[(wid * 16 + g + 8) * PSS];

    // ---- Q fragments (persistent), staged in two 32-col halves ----
    uint32_t aq[8][4];
#pragma unroll
    for (int half = 0; half < 2; half++) {
        __syncthreads();
        for (int i = tid; i < 128 * 32; i += 256) {
            int r = i >> 5, d = i & 31;
            Ps[r * PSS + d] = qbase[(size_t)r * DIMN + half * 32 + d] * SCALE_F;
        }
        __syncthreads();
#pragma unroll
        for (int k2 = 0; k2 < 4; k2++) {
            int kk = half * 4 + k2;
            aq[kk][0] = cvt_tf32(prow0[k2 * 8 + tig]);
            aq[kk][1] = cvt_tf32(prow1[k2 * 8 + tig]);
            aq[kk][2] = cvt_tf32(prow0[k2 * 8 + tig + 4]);
            aq[kk][3] = cvt_tf32(prow1[k2 * 8 + tig + 4]);
        }
    }

    float o[8][4];
#pragma unroll
    for (int nf = 0; nf < 8; nf++)
#pragma unroll
        for (int r = 0; r < 4; r++) o[nf][r] = 0.f;
    float m0 = negInf(), m1 = negInf(), l0s = 0.f, l1s = 0.f;

    for (int kt = 0; kt < LSEQ / AKT; kt++) {
        __syncthreads();
        for (int i = tid; i < AKT * 16; i += 256) {
            int r = i >> 4, c4 = (i & 15) * 4;
            *(float4*)&Ks[r * KSS + c4] =
                tf32r4(*(const float4*)&kbase[((size_t)kt * AKT + r) * DIMN + c4]);
            *(float4*)&Vs[r * VSS + c4] =
                tf32r4(*(const float4*)&vbase[((size_t)kt * AKT + r) * DIMN + c4]);
        }
        __syncthreads();

        // ---- scores S = Q K^T ----
        float s[4][4];
#pragma unroll
        for (int nf = 0; nf < 4; nf++)
#pragma unroll
            for (int r = 0; r < 4; r++) s[nf][r] = 0.f;
#pragma unroll
        for (int kk = 0; kk < 8; kk++) {
#pragma unroll
            for (int nf = 0; nf < 4; nf++) {
                uint32_t bb[2];
                bb[0] = __float_as_uint(Ks[(nf * 8 + g) * KSS + kk * 8 + tig]);
                bb[1] = __float_as_uint(Ks[(nf * 8 + g) * KSS + kk * 8 + tig + 4]);
                mma_tf32(s[nf], aq[kk], bb);
            }
        }

        // ---- online softmax (rows g, g+8) ----
        float t0 = negInf(), t1 = negInf();
#pragma unroll
        for (int nf = 0; nf < 4; nf++) {
            t0 = fmaxf(t0, fmaxf(s[nf][0], s[nf][1]));
            t1 = fmaxf(t1, fmaxf(s[nf][2], s[nf][3]));
        }
#pragma unroll
        for (int off = 1; off < 4; off <<= 1) {
            t0 = fmaxf(t0, __shfl_xor_sync(0xffffffffu, t0, off));
            t1 = fmaxf(t1, __shfl_xor_sync(0xffffffffu, t1, off));
        }
        float mn0 = fmaxf(m0, t0), mn1 = fmaxf(m1, t1);
        float c0 = __expf(m0 - mn0), c1 = __expf(m1 - mn1);
        l0s *= c0; l1s *= c1;
#pragma unroll
        for (int nf = 0; nf < 8; nf++) {
            o[nf][0] *= c0; o[nf][1] *= c0;
            o[nf][2] *= c1; o[nf][3] *= c1;
        }
        float ls0 = 0.f, ls1 = 0.f;
#pragma unroll
        for (int nf = 0; nf < 4; nf++) {
            float p0 = __expf(s[nf][0] - mn0);
            float p1 = __expf(s[nf][1] - mn0);
            float p2 = __expf(s[nf][2] - mn1);
            float p3 = __expf(s[nf][3] - mn1);
            ls0 += p0 + p1; ls1 += p2 + p3;
            prow0[nf * 8 + 2 * tig]     = tf32r(p0);
            prow0[nf * 8 + 2 * tig + 1] = tf32r(p1);
            prow1[nf * 8 + 2 * tig]     = tf32r(p2);
            prow1[nf * 8 + 2 * tig + 1] = tf32r(p3);
        }
#pragma unroll
        for (int off = 1; off < 4; off <<= 1) {
            ls0 += __shfl_xor_sync(0xffffffffu, ls0, off);
            ls1 += __shfl_xor_sync(0xffffffffu, ls1, off);
        }
        l0s += ls0; l1s += ls1;
        m0 = mn0; m1 = mn1;
        __syncwarp();

        // ---- O += P V ----
#pragma unroll
        for (int kk = 0; kk < 4; kk++) {
            uint32_t ap[4];
            ap[0] = __float_as_uint(prow0[kk * 8 + tig]);
            ap[1] = __float_as_uint(prow1[kk * 8 + tig]);
            ap[2] = __float_as_uint(prow0[kk * 8 + tig + 4]);
            ap[3] = __float_as_uint(prow1[kk * 8 + tig + 4]);
#pragma unroll
            for (int nf = 0; nf < 8; nf++) {
                uint32_t bb[2];
                bb[0] = __float_as_uint(Vs[(kk * 8 + tig) * VSS + nf * 8 + g]);
                bb[1] = __float_as_uint(Vs[(kk * 8 + tig + 4) * VSS + nf * 8 + g]);
                mma_tf32(o[nf], ap, bb);
            }
        }
    }

    // ---- normalize + max-pool via staging, two 32-dim halves ----
    float inv0 = 1.f / l0s, inv1 = 1.f / l1s;
#pragma unroll
    for (int nf = 0; nf < 8; nf++) {
        o[nf][0] *= inv0; o[nf][1] *= inv0;
        o[nf][2] *= inv1; o[nf][3] *= inv1;
    }
#pragma unroll
    for (int half = 0; half < 2; half++) {
        __syncthreads();
#pragma unroll
        for (int nf2 = 0; nf2 < 4; nf2++) {
            int nf = half * 4 + nf2;
            prow0[nf2 * 8 + 2 * tig]     = o[nf][0];
            prow0[nf2 * 8 + 2 * tig + 1] = o[nf][1];
            prow1[nf2 * 8 + 2 * tig]     = o[nf][2];
            prow1[nf2 * 8 + 2 * tig + 1] = o[nf][3];
        }
        __syncthreads();
        if (tid < 32) {
            float mx = negInf();
            for (int r = 0; r < 128; r++) mx = fmaxf(mx, Ps[r * PSS + tid]);
            atomicMaxF(&g_a1[b * DIMN + h * HDN + half * 32 + tid], mx);
        }
    }
}

// ============================================================
// 4a) attn2 phase A: partial channel scores over one L-chunk.
// ============================================================
__global__ __launch_bounds__(320) void attn2_score_kernel() {
    __shared__ float s_a[8 * 5 * 64];
    __shared__ float s_b[8 * 5 * 64];

    const int d = threadIdx.x, s = threadIdx.y;
    const int tid = s * 64 + d;
    const int wh = blockIdx.x, lc = blockIdx.y;
    const int w = wh / HEADSN, h = wh % HEADSN;

    const float* qb = g_q + (size_t)w * SHOTN * LSEQ * DIMN + h * HDN;
    const float* kb = g_k + (size_t)w * SHOTN * LSEQ * DIMN + h * HDN;

    float acc[5] = {0.f, 0.f, 0.f, 0.f, 0.f};

    for (int l0 = 0; l0 < LPC; l0 += 8) {
        __syncthreads();
        for (int i = tid; i < 2560; i += 320) {
            int dd = i & 63, tt = (i >> 6) % 5, li = i / 320;
            size_t off = ((size_t)tt * LSEQ + lc * LPC + l0 + li) * DIMN + dd;
            s_a[i] = qb[off];
            s_b[i] = kb[off];
        }
        __syncthreads();
#pragma unroll
        for (int li = 0; li < 8; li++) {
            float qv = s_a[li * 320 + s * 64 + d];
#pragma unroll
            for (int t = 0; t < 5; t++)
                acc[t] += qv * s_b[li * 320 + t * 64 + d];
        }
    }

    float* dst = g_s2p + (((size_t)wh * LCH + lc) * HDN + d) * 25 + s * 5;
#pragma unroll
    for (int t = 0; t < 5; t++) dst[t] = acc[t];
}

// ============================================================
// 4b) attn2 phase B: ordered reduce + softmax -> pw
// ============================================================
__global__ __launch_bounds__(320) void attn2_softmax_kernel() {
    const int d = threadIdx.x, s = threadIdx.y;
    const int wh = blockIdx.x;

    float acc[5];
#pragma unroll
    for (int t = 0; t < 5; t++) {
        float v = 0.f;
#pragma unroll
        for (int c = 0; c < LCH; c++)
            v += g_s2p[(((size_t)wh * LCH + c) * HDN + d) * 25 + s * 5 + t];
        acc[t] = v * SCALE_F;
    }

    float mx = negInf();
#pragma unroll
    for (int t = 0; t < 5; t++) mx = fmaxf(mx, acc[t]);
    float pw[5], sum = 0.f;
#pragma unroll
    for (int t = 0; t < 5; t++) { pw[t] = __expf(acc[t] - mx); sum += pw[t]; }
    float inv = 1.f / sum;
#pragma unroll
    for (int t = 0; t < 5; t++)
        g_pw[((size_t)wh * HDN + d) * 25 + s * 5 + t] = pw[t] * inv;
}

// ============================================================
// 4c) attn2 phase C: weighted V + max-pool, atomicMax.
// ============================================================
__global__ __launch_bounds__(320) void attn2_apply_kernel() {
    __shared__ float s_v[8 * 5 * 64];

    const int d = threadIdx.x, s = threadIdx.y;
    const int tid = s * 64 + d;
    const int wh = blockIdx.x, lc = blockIdx.y;
    const int w = wh / HEADSN, h = wh % HEADSN;

    const float* vb = g_v + (size_t)w * SHOTN * LSEQ * DIMN + h * HDN;

    float pw[5];
#pragma unroll
    for (int t = 0; t < 5; t++)
        pw[t] = g_pw[((size_t)wh * HDN + d) * 25 + s * 5 + t];

    float amax = negInf();
    for (int l0 = 0; l0 < LPC; l0 += 8) {
        __syncthreads();
        for (int i = tid; i < 2560; i += 320) {
            int dd = i & 63, tt = (i >> 6) % 5, li = i / 320;
            s_v[i] = vb[((size_t)tt * LSEQ + lc * LPC + l0 + li) * DIMN + dd];
        }
        __syncthreads();
#pragma unroll
        for (int li = 0; li < 8; li++) {
            float val = 0.f;
#pragma unroll
            for (int t = 0; t < 5; t++)
                val += pw[t] * s_v[li * 320 + t * 64 + d];
            amax = fmaxf(amax, val);
        }
    }

    atomicMaxF(&g_a2[((size_t)w * SHOTN + s) * DIMN + h * HDN + d], amax);
}

// ============================================================
// 5) LayerNorm both branches + combine + tanh-dot with wp
// ============================================================
__device__ __forceinline__ float blockReduceSum256(float v, float* red) {
#pragma unroll
    for (int o = 16; o > 0; o >>= 1) v += __shfl_down_sync(0xffffffffu, v, o);
    __syncthreads();
    if ((threadIdx.x & 31) == 0) red[threadIdx.x >> 5] = v;
    __syncthreads();
    float tot = 0.f;
#pragma unroll
    for (int i = 0; i < 8; i++) tot += red[i];
    return tot;
}

__global__ __launch_bounds__(256) void ln_kernel(
    const float* __restrict__ gamma, const float* __restrict__ beta,
    const float* __restrict__ wp, const float* __restrict__ bp)
{
    __shared__ float red[8];
    const int row = blockIdx.x, tid = threadIdx.x;
    const float* r1 = g_a1 + row * DIMN;
    const float* r2 = g_a2 + row * DIMN;

    float s1 = 0, q1 = 0, s2 = 0, q2 = 0;
    for (int j = tid; j < DIMN; j += 256) {
        float x = r1[j]; s1 += x; q1 += x * x;
        float y = r2[j]; s2 += y; q2 += y * y;
    }
    s1 = blockReduceSum256(s1, red);
    q1 = blockReduceSum256(q1, red);
    s2 = blockReduceSum256(s2, red);
    q2 = blockReduceSum256(q2, red);

    const float invd = 1.f / DIMN;
    float m1 = s1 * invd, m2 = s2 * invd;
    float rs1 = rsqrtf(q1 * invd - m1 * m1 + 1e-5f);
    float rs2 = rsqrtf(q2 * invd - m2 * m2 + 1e-5f);

    float dotv = 0.f;
    for (int j = tid; j < DIMN; j += 256) {
        float g = gamma[j], bb = beta[j];
        float l1 = (r1[j] - m1) * rs1 * g + bb;
        float l2 = (r2[j] - m2) * rs2 * g + bb;
        float at = 0.5f * (l1 + l2);
        g_attn[row * DIMN + j] = at;
        dotv += tanhf(at) * wp[j];
    }
    dotv = blockReduceSum256(dotv, red);
    if (tid == 0) g_z[row] = dotv + bp[0];
}

// ============================================================
// 6) softmax over shots + weighted sum of attn -> c[w, dim]
// ============================================================
__global__ __launch_bounds__(256) void weight_kernel() {
    const int w = blockIdx.x, tid = threadIdx.x;
    float zz[5], mx = negInf();
#pragma unroll
    for (int t = 0; t < 5; t++) { zz[t] = g_z[w * 5 + t]; mx = fmaxf(mx, zz[t]); }
    float pw[5], sum = 0.f;
#pragma unroll
    for (int t = 0; t < 5; t++) { pw[t] = __expf(zz[t] - mx); sum += pw[t]; }
    float inv = 1.f / sum;
    for (int j = tid; j < DIMN; j += 256) {
        float acc = 0.f;
#pragma unroll
        for (int t = 0; t < 5; t++)
            acc += pw[t] * g_attn[((size_t)w * 5 + t) * DIMN + j];
        g_c[w * DIMN + j] = acc * inv;
    }
}

// ============================================================
// 7) out[w,j] = c[w,:] . Wo[j,:] + SHOT*bo[j]
// ============================================================
__global__ __launch_bounds__(256) void out_kernel(
    const float* __restrict__ Wo, const float* __restrict__ bo,
    float* __restrict__ out)
{
    const int w = blockIdx.y;
    const int warp = threadIdx.x >> 5, lane = threadIdx.x & 31;
    const int j = blockIdx.x * 8 + warp;
    const float* cr = g_c + w * DIMN;
    const float* wr = Wo + (size_t)j * DIMN;
    float s = 0.f;
    for (int kk = lane; kk < DIMN; kk += 32) s += cr[kk] * wr[kk];
#pragma unroll
    for (int o = 16; o > 0; o >>= 1) s += __shfl_down_sync(0xffffffffu, s, o);
    if (lane == 0) out[w * DIMN + j] = s + (float)SHOTN * bo[j];
}

// ============================================================
// launcher
// ============================================================
extern "C" void kernel_launch(void* const* d_in, const int* in_sizes, int n_in,
                              void* d_out, int out_size)
{
    const float* x     = (const float*)d_in[0];
    const float* Wq    = (const float*)d_in[1];
    const float* bq    = (const float*)d_in[2];
    const float* Wk    = (const float*)d_in[3];
    const float* bk    = (const float*)d_in[4];
    const float* Wv    = (const float*)d_in[5];
    const float* bv    = (const float*)d_in[6];
    const float* gamma = (const float*)d_in[7];
    const float* beta  = (const float*)d_in[8];
    const float* wp    = (const float*)d_in[9];
    const float* bp    = (const float*)d_in[10];
    const float* Wo    = (const float*)d_in[11];
    const float* bo    = (const float*)d_in[12];
    float* out = (float*)d_out;

    float *qp, *kp, *vp;
    cudaGetSymbolAddress((void**)&qp, g_q);
    cudaGetSymbolAddress((void**)&kp, g_k);
    cudaGetSymbolAddress((void**)&vp, g_v);

    gemm_tc_kernel<<<dim3(DIMN / 128, (NB * LSEQ) / 128, 3), 256>>>(
        x, Wq, Wk, Wv, bq, bk, bv, qp, kp, vp);

    init_kernel<<<(2 * NB * DIMN + 255) / 256, 256>>>();

    dim3 agrid(LSEQ / 128, HEADSN, NB);          // (4, 12, 25)
    attn1_kernel<<<agrid, 256>>>();

    attn2_score_kernel<<<dim3(WAYN * HEADSN, LCH), dim3(64, 5)>>>();
    attn2_softmax_kernel<<<WAYN * HEADSN, dim3(64, 5)>>>();
    attn2_apply_kernel<<<dim3(WAYN * HEADSN, LCH), dim3(64, 5)>>>();

    ln_kernel<<<NB, 256>>>(gamma, beta, wp, bp);
    weight_kernel<<<WAYN, 256>>>();
    out_kernel<<<dim3(DIMN / 8, WAYN), 256>>>(Wo, bo, out);
}